// round 14
// baseline (speedup 1.0000x reference)
#include <cuda_runtime.h>
#include <cstdint>

#define BB 4
#define NN 2048
#define KK 16
#define DD 64
#define NK (NN*KK)
#define EPSV 1e-5f

// ---------------- f32x2 packed FMA helpers ----------------
__device__ __forceinline__ uint64_t pk2(float lo, float hi){
    uint64_t r;
    asm("mov.b64 %0, {%1, %2};" : "=l"(r) : "r"(__float_as_uint(lo)), "r"(__float_as_uint(hi)));
    return r;
}
__device__ __forceinline__ void fma2(uint64_t& d, uint64_t a, uint64_t b){
    asm("fma.rn.f32x2 %0, %1, %2, %0;" : "+l"(d) : "l"(a), "l"(b));
}
__device__ __forceinline__ void unpk2(uint64_t v, float& lo, float& hi){
    uint32_t l, h;
    asm("mov.b64 {%0, %1}, %2;" : "=r"(l), "=r"(h) : "l"(v));
    lo = __uint_as_float(l); hi = __uint_as_float(h);
}

// ---------------- scratch ----------------
__device__ float g_hx  [BB*128*NN];
__device__ float g_p1  [BB*128*NN];
__device__ float g_p2  [BB*128*NN];
__device__ float g_p3  [BB*128*NN];
__device__ float g_x   [BB*DD*NN];
__device__ float g_qkvt[BB*NN*192];
__device__ int   g_idx [BB*KK*NN];
__device__ float g_G   [BB*DD*NK];
__device__ float g_vr  [BB*DD*NK];
__device__ float g_at  [BB*DD*NK];
__device__ float g_fold[640];
__device__ float g_fd1f[256];
__device__ float g_wT  [4*64*64];
__device__ float g_w_bt1s[480*128];
__device__ float g_b_bt1s[128];
__device__ float g_w_xqkv[128*256];
__device__ float g_b_xqkv[256];
__device__ float g_w_fd2 [64*64];
__device__ float g_w_fg1 [64*256];
__device__ float g_w_fg2 [256*64];
__device__ float g_w_m41 [64*64];

// ---------------- prep ----------------
__global__ void prep_kernel(const float* __restrict__ fd_g, const float* __restrict__ fd1_b,
                            const float* __restrict__ fd_bb,
                            const float* __restrict__ fg_g, const float* __restrict__ fg1_b,
                            const float* __restrict__ fg_bb,
                            const float* __restrict__ at_w, const float* __restrict__ fd1_w,
                            const float* __restrict__ bt1_w, const float* __restrict__ bt1_b,
                            const float* __restrict__ bts_w, const float* __restrict__ bts_b,
                            const float* __restrict__ fd2_w,
                            const float* __restrict__ fg1_w, const float* __restrict__ fg2_w,
                            const float* __restrict__ m41_w)
{
    int t = blockIdx.x * blockDim.x + threadIdx.x;
    float inv = rsqrtf(1.f + EPSV);
    if (t < 64) {
        float s = fd_g[t]*inv;
        g_fd1f[t]       = fd1_w[t*3]   * s;
        g_fd1f[64+t]    = fd1_w[t*3+1] * s;
        g_fd1f[128+t]   = fd1_w[t*3+2] * s;
        g_fd1f[192+t]   = fd1_b[t]*s + fd_bb[t];
    }
    if (t < 256) { float s = fg_g[t]*inv; g_fold[128+t] = s; g_fold[384+t] = fg1_b[t]*s + fg_bb[t]; }
    if (t < 16384) {
        int r = t & 3, o = (t >> 2) & 63, c = t >> 8;
        g_wT[r*4096 + c*64 + o] = at_w[t];
        { int k = t >> 8, m = t & 255; g_w_fg1[k*256 + m] = fg1_w[m*64 + k]; }
        { int k = t >> 6, m = t & 63;  g_w_fg2[k*64 + m]  = fg2_w[m*256 + k]; }
    }
    if (t < 61440) { int k = t >> 7, m = t & 127;
        g_w_bt1s[t] = (m < 64) ? bt1_w[m*480 + k] : bts_w[(m-64)*480 + k]; }
    if (t < 128) g_b_bt1s[t] = (t < 64) ? bt1_b[t] : bts_b[t-64];
    if (t < 4096) { int k = t >> 6, m = t & 63;
        g_w_fd2[t] = fd2_w[m*64+k];
        g_w_m41[t] = m41_w[m*64+k]; }
}

// ---------------- prep2: composite x/qkv weights ----------------
__global__ void prep2_kernel(const float* __restrict__ bt2_w, const float* __restrict__ bt2_b,
                             const float* __restrict__ q_w, const float* __restrict__ q_b,
                             const float* __restrict__ k_w, const float* __restrict__ k_b,
                             const float* __restrict__ v_w, const float* __restrict__ v_b)
{
    int t = blockIdx.x * blockDim.x + threadIdx.x;
    if (t < 32768) {
        int m = t & 255, k = t >> 8;
        float val;
        if (k < 64) {
            if (m < 64) val = bt2_w[m*64 + k];
            else {
                int mm = m - 64;
                const float* wr = (mm < 64) ? q_w + mm*64
                                 : (mm < 128 ? k_w + (mm-64)*64 : v_w + (mm-128)*64);
                float s = 0.f;
                #pragma unroll 8
                for (int c = 0; c < 64; c++) s += wr[c] * bt2_w[c*64 + k];
                val = s;
            }
        } else {
            int kk = k - 64;
            if (m < 64) val = (m == kk) ? 1.f : 0.f;
            else {
                int mm = m - 64;
                val = (mm < 64) ? q_w[mm*64 + kk]
                     : (mm < 128 ? k_w[(mm-64)*64 + kk] : v_w[(mm-128)*64 + kk]);
            }
        }
        g_w_xqkv[k*256 + m] = val;
    } else if (t < 33024) {
        int m = t - 32768;
        if (m < 64) g_b_xqkv[m] = bt2_b[m];
        else {
            int mm = m - 64;
            const float* wr = (mm < 64) ? q_w + mm*64
                             : (mm < 128 ? k_w + (mm-64)*64 : v_w + (mm-128)*64);
            float s = (mm < 64) ? q_b[mm] : (mm < 128 ? k_b[mm-64] : v_b[mm-128]);
            #pragma unroll 8
            for (int c = 0; c < 64; c++) s += wr[c] * bt2_b[c];
            g_b_xqkv[m] = s;
        }
    }
}

// ---------------- KNN ----------------
__global__ void knn_kernel(const float* __restrict__ xyz)
{
    __shared__ float sx[NN], sy[NN], sz[NN], ssq[NN];
    int b  = blockIdx.x >> 7;
    int n0 = (blockIdx.x & 127) * 16;
    const float* xb = xyz + b*3*NN;
    for (int m = threadIdx.x; m < NN; m += blockDim.x) {
        float px = xb[m], py = xb[NN+m], pz = xb[2*NN+m];
        sx[m]=px; sy[m]=py; sz[m]=pz; ssq[m] = px*px + py*py + pz*pz;
    }
    __syncthreads();
    int warp = threadIdx.x >> 5, lane = threadIdx.x & 31;
    int n = n0 + warp;
    float px = sx[n], py = sy[n], pz = sz[n], sqn = ssq[n];

    float bv[17]; int bi[17];
    #pragma unroll
    for (int i = 0; i < 17; i++) { bv[i] = 3.4e38f; bi[i] = 0x7fffffff; }
    for (int m = lane; m < NN; m += 32) {
        float d2 = sqn + ssq[m] - 2.f*(px*sx[m] + py*sy[m] + pz*sz[m]);
        if (d2 < bv[16]) {
            bv[16] = d2; bi[16] = m;
            #pragma unroll
            for (int s = 16; s > 0; --s)
                if (bv[s] < bv[s-1]) {
                    float tv = bv[s]; bv[s] = bv[s-1]; bv[s-1] = tv;
                    int   ti = bi[s]; bi[s] = bi[s-1]; bi[s-1] = ti;
                }
        }
    }
    for (int t = 0; t < 17; ++t) {
        float hv = bv[0]; int hi = bi[0];
        float v = hv; int id = hi;
        #pragma unroll
        for (int off = 16; off; off >>= 1) {
            float ov = __shfl_xor_sync(0xffffffffu, v, off);
            int   oi = __shfl_xor_sync(0xffffffffu, id, off);
            if (ov < v || (ov == v && oi < id)) { v = ov; id = oi; }
        }
        if (t > 0 && lane == 0) g_idx[b*KK*NN + (t-1)*NN + n] = id;
        if (hv == v && hi == id) {
            #pragma unroll
            for (int s = 0; s < 16; ++s) { bv[s] = bv[s+1]; bi[s] = bi[s+1]; }
            bv[16] = 3.4e38f; bi[16] = 0x7fffffff;
        }
    }
}

// ---------------- bt1s split-K(4) GEMM ----------------
__global__ void __launch_bounds__(128) bt1s_kernel(const float* __restrict__ feature)
{
    constexpr int KC = 8;
    __shared__ __align__(16) float sW[2][KC][128];
    __shared__ __align__(16) float sX[2][KC][64];
    int tid = threadIdx.x;
    int b = blockIdx.z;
    int split = blockIdx.y;
    int bn0 = blockIdx.x * 64;
    const float* Wt = g_w_bt1s + (size_t)split*120*128;
    const float* Xb = feature + (size_t)b*480*NN + (size_t)split*120*NN;
    float* Cb = (split == 0 ? g_hx : (split == 1 ? g_p1 : (split == 2 ? g_p2 : g_p3)))
                + (size_t)b*128*NN;

    float4 wr[2], xr1;
    uint64_t acc2[8][4];
    #pragma unroll
    for (int i = 0; i < 8; i++)
        #pragma unroll
        for (int j = 0; j < 4; j++) acc2[i][j] = 0ull;
    int tx = tid & 7, ty = tid >> 3;
    int rm = ty*8, rn = tx*8;

    {
        #pragma unroll
        for (int i = 0; i < 2; i++) { int t = tid + i*128; int k = t>>5, m4 = (t&31)*4;
            wr[i] = *(const float4*)(Wt + (size_t)k*128 + m4); }
        { int k = tid >> 4, n4 = (tid & 15)*4;
          xr1 = *(const float4*)(Xb + (size_t)k*NN + bn0 + n4); }
        #pragma unroll
        for (int i = 0; i < 2; i++) { int t = tid + i*128; int k = t>>5, m4 = (t&31)*4;
            *(float4*)&sW[0][k][m4] = wr[i]; }
        { int k = tid >> 4, n4 = (tid & 15)*4; *(float4*)&sX[0][k][n4] = xr1; }
    }
    __syncthreads();

    for (int c = 0; c < 15; ++c) {
        if (c + 1 < 15) {
            int k0 = (c+1)*KC;
            #pragma unroll
            for (int i = 0; i < 2; i++) { int t = tid + i*128; int k = t>>5, m4 = (t&31)*4;
                wr[i] = *(const float4*)(Wt + (size_t)(k0+k)*128 + m4); }
            { int k = tid >> 4, n4 = (tid & 15)*4;
              xr1 = *(const float4*)(Xb + (size_t)(k0 + (tid>>4))*NN + bn0 + n4); }
        }
        int buf = c & 1;
        #pragma unroll
        for (int k = 0; k < KC; ++k) {
            ulonglong2 bq0 = *(const ulonglong2*)&sX[buf][k][rn];
            ulonglong2 bq1 = *(const ulonglong2*)&sX[buf][k][rn+4];
            uint64_t bp[4] = {bq0.x, bq0.y, bq1.x, bq1.y};
            float4 a0 = *(const float4*)&sW[buf][k][rm];
            float4 a1 = *(const float4*)&sW[buf][k][rm+4];
            float av[8] = {a0.x,a0.y,a0.z,a0.w,a1.x,a1.y,a1.z,a1.w};
            #pragma unroll
            for (int i = 0; i < 8; i++) {
                uint64_t ap = pk2(av[i], av[i]);
                #pragma unroll
                for (int j = 0; j < 4; j++) fma2(acc2[i][j], ap, bp[j]);
            }
        }
        if (c + 1 < 15) {
            int nb = (c+1) & 1;
            #pragma unroll
            for (int i = 0; i < 2; i++) { int t = tid + i*128; int k = t>>5, m4 = (t&31)*4;
                *(float4*)&sW[nb][k][m4] = wr[i]; }
            { int k = tid >> 4, n4 = (tid & 15)*4; *(float4*)&sX[nb][k][n4] = xr1; }
        }
        __syncthreads();
    }

    #pragma unroll
    for (int i = 0; i < 8; i++) {
        int row = rm + i;
        float v[8];
        #pragma unroll
        for (int j = 0; j < 4; j++) unpk2(acc2[i][j], v[2*j], v[2*j+1]);
        *(float4*)(Cb + (size_t)row*NN + bn0 + rn)     = make_float4(v[0],v[1],v[2],v[3]);
        *(float4*)(Cb + (size_t)row*NN + bn0 + rn + 4) = make_float4(v[4],v[5],v[6],v[7]);
    }
}

__device__ __forceinline__ float4 hx_load(const float* p0, const float* p1,
                                          const float* p2, const float* p3,
                                          size_t off, int kglob)
{
    float4 a = *(const float4*)(p0 + off);
    float4 c = *(const float4*)(p1 + off);
    float4 d = *(const float4*)(p2 + off);
    float4 e = *(const float4*)(p3 + off);
    float bs = g_b_bt1s[kglob];
    float4 r = make_float4(a.x+c.x+d.x+e.x+bs, a.y+c.y+d.y+e.y+bs,
                           a.z+c.z+d.z+e.z+bs, a.w+c.w+d.w+e.w+bs);
    if (kglob < 64) {
        r.x = fmaxf(r.x, 0.f); r.y = fmaxf(r.y, 0.f);
        r.z = fmaxf(r.z, 0.f); r.w = fmaxf(r.w, 0.f);
    }
    return r;
}

// ---------------- xqkv ----------------
__global__ void __launch_bounds__(128) xqkv_kernel()
{
    constexpr int KC = 8;
    __shared__ __align__(16) float sW[2][KC][64];
    __shared__ __align__(16) float sX[2][KC][128];
    int tid = threadIdx.x;
    int b = blockIdx.z;
    int bn0 = blockIdx.x * 128;
    int bm0 = blockIdx.y * 64;
    const float* p0 = g_hx + (size_t)b * 128 * NN;
    const float* p1 = g_p1 + (size_t)b * 128 * NN;
    const float* p2 = g_p2 + (size_t)b * 128 * NN;
    const float* p3 = g_p3 + (size_t)b * 128 * NN;

    float4 wr1, xr[2];
    uint64_t acc2[8][4];
    #pragma unroll
    for (int i = 0; i < 8; i++)
        #pragma unroll
        for (int j = 0; j < 4; j++) acc2[i][j] = 0ull;
    int tx = tid & 15, ty = tid >> 4;
    int rm = ty*8, rn = tx*8;
    int wk = tid >> 4;
    int wm = (tid & 15) * 4;

    {
        wr1 = *(const float4*)(g_w_xqkv + (size_t)wk*256 + bm0 + wm);
        #pragma unroll
        for (int i = 0; i < 2; i++) { int t = tid + i*128; int k = t >> 5, n4 = t & 31;
            xr[i] = hx_load(p0, p1, p2, p3, (size_t)k*NN + bn0 + n4*4, k); }
        *(float4*)&sW[0][wk][wm] = wr1;
        #pragma unroll
        for (int i = 0; i < 2; i++) { int t = tid + i*128; int k = t >> 5, n4 = t & 31;
            *(float4*)&sX[0][k][n4*4] = xr[i]; }
    }
    __syncthreads();

    for (int c = 0; c < 16; ++c) {
        if (c + 1 < 16) {
            int k0 = (c+1)*KC;
            wr1 = *(const float4*)(g_w_xqkv + (size_t)(k0+wk)*256 + bm0 + wm);
            #pragma unroll
            for (int i = 0; i < 2; i++) { int t = tid + i*128; int k = t >> 5, n4 = t & 31;
                xr[i] = hx_load(p0, p1, p2, p3, (size_t)(k0+k)*NN + bn0 + n4*4, k0+k); }
        }
        int buf = c & 1;
        #pragma unroll
        for (int k = 0; k < KC; ++k) {
            ulonglong2 bq0 = *(const ulonglong2*)&sX[buf][k][rn];
            ulonglong2 bq1 = *(const ulonglong2*)&sX[buf][k][rn+4];
            uint64_t bp[4] = {bq0.x, bq0.y, bq1.x, bq1.y};
            float4 a0 = *(const float4*)&sW[buf][k][rm];
            float4 a1 = *(const float4*)&sW[buf][k][rm+4];
            float av[8] = {a0.x,a0.y,a0.z,a0.w,a1.x,a1.y,a1.z,a1.w};
            #pragma unroll
            for (int i = 0; i < 8; i++) {
                uint64_t ap = pk2(av[i], av[i]);
                #pragma unroll
                for (int j = 0; j < 4; j++) fma2(acc2[i][j], ap, bp[j]);
            }
        }
        if (c + 1 < 16) {
            int nb = (c+1) & 1;
            *(float4*)&sW[nb][wk][wm] = wr1;
            #pragma unroll
            for (int i = 0; i < 2; i++) { int t = tid + i*128; int k = t >> 5, n4 = t & 31;
                *(float4*)&sX[nb][k][n4*4] = xr[i]; }
        }
        __syncthreads();
    }

    float v[8][8];
    #pragma unroll
    for (int i = 0; i < 8; i++) {
        float bs = g_b_xqkv[bm0 + rm + i];
        #pragma unroll
        for (int j = 0; j < 4; j++) {
            float lo, hi;
            unpk2(acc2[i][j], lo, hi);
            v[i][2*j] = lo + bs; v[i][2*j+1] = hi + bs;
        }
    }
    if (blockIdx.y == 0) {
        #pragma unroll
        for (int i = 0; i < 8; i++) {
            int row = rm + i;
            *(float4*)(g_x + ((size_t)(b*64+row))*NN + bn0 + rn)
                = make_float4(v[i][0],v[i][1],v[i][2],v[i][3]);
            *(float4*)(g_x + ((size_t)(b*64+row))*NN + bn0 + rn + 4)
                = make_float4(v[i][4],v[i][5],v[i][6],v[i][7]);
        }
    } else {
        int qbase = bm0 + rm - 64;
        #pragma unroll
        for (int j = 0; j < 8; j++) {
            int n = bn0 + rn + j;
            float* dst = g_qkvt + ((size_t)(b*NN) + n)*192 + qbase;
            *(float4*)dst       = make_float4(v[0][j],v[1][j],v[2][j],v[3][j]);
            *(float4*)(dst + 4) = make_float4(v[4][j],v[5][j],v[6][j],v[7][j]);
        }
    }
}

// ---------------- fused posenc(fd1) + fd2 GEMM + G/Vrel build ----------------
__global__ void __launch_bounds__(128) fd2gv_kernel(const float* __restrict__ xyz,
                                                    const float* __restrict__ fd2_b)
{
    extern __shared__ __align__(16) float dynA[];
    float* sW = dynA;
    float* sT = dynA + 64*68;
    float* sF = dynA + 64*68 + 64*132;
    int tid = threadIdx.x;
    int b = blockIdx.z;
    int bn0 = blockIdx.x * 128;
    int tx = tid & 15, ty = tid >> 4;
    int rn = tx*8, rm = ty*8;

    #pragma unroll
    for (int i = 0; i < 8; i++) { int t = tid + i*128; int k = t>>4, m4 = (t&15)*4;
        *(float4*)&sW[k*68 + m4] = *(const float4*)(g_w_fd2 + k*64 + m4); }
    sF[tid] = g_fd1f[tid];
    sF[tid+128] = g_fd1f[tid+128];

    int col = bn0 + tid;
    int np = col >> 4, jp = col & 15;
    int idg = g_idx[b*KK*NN + jp*NN + np];
    const float* xb = xyz + b*3*NN;
    float rx = xb[np]      - xb[idg];
    float ry = xb[NN+np]   - xb[NN+idg];
    float rz = xb[2*NN+np] - xb[2*NN+idg];
    __syncthreads();
    #pragma unroll 8
    for (int m = 0; m < 64; ++m) {
        float v = sF[m]*rx + sF[64+m]*ry + sF[128+m]*rz + sF[192+m];
        sT[m*132 + tid] = fmaxf(v, 0.f);
    }
    __syncthreads();

    uint64_t acc[8][4];
    #pragma unroll
    for (int i = 0; i < 8; i++)
        #pragma unroll
        for (int j = 0; j < 4; j++) acc[i][j] = 0ull;
    #pragma unroll 4
    for (int k = 0; k < 64; ++k) {
        ulonglong2 b0 = *(const ulonglong2*)&sT[k*132 + rn];
        ulonglong2 b1 = *(const ulonglong2*)&sT[k*132 + rn + 4];
        float4 a0 = *(const float4*)&sW[k*68 + rm];
        float4 a1 = *(const float4*)&sW[k*68 + rm + 4];
        float av[8] = {a0.x,a0.y,a0.z,a0.w,a1.x,a1.y,a1.z,a1.w};
        #pragma unroll
        for (int i = 0; i < 8; i++) {
            uint64_t ap = pk2(av[i], av[i]);
            fma2(acc[i][0], ap, b0.x); fma2(acc[i][1], ap, b0.y);
            fma2(acc[i][2], ap, b1.x); fma2(acc[i][3], ap, b1.y);
        }
    }

    int col0 = bn0 + rn;
    int n = col0 >> 4, j0 = col0 & 15;
    float qv[8], bs[8];
    const float* qp = g_qkvt + ((size_t)b*NN + n)*192 + rm;
    *(float4*)&qv[0] = *(const float4*)qp;
    *(float4*)&qv[4] = *(const float4*)(qp + 4);
    #pragma unroll
    for (int i = 0; i < 8; i++) bs[i] = fd2_b[rm + i];

    #pragma unroll
    for (int g = 0; g < 2; ++g) {
        float ka[4][8], va[4][8];
        #pragma unroll
        for (int jj = 0; jj < 4; jj++) {
            int id = g_idx[b*KK*NN + (j0 + g*4 + jj)*NN + n];
            const float* kp = g_qkvt + ((size_t)b*NN + id)*192 + 64 + rm;
            *(float4*)&ka[jj][0] = *(const float4*)kp;
            *(float4*)&ka[jj][4] = *(const float4*)(kp + 4);
            *(float4*)&va[jj][0] = *(const float4*)(kp + 64);
            *(float4*)&va[jj][4] = *(const float4*)(kp + 68);
        }
        #pragma unroll
        for (int i = 0; i < 8; i++) {
            float p0,p1,p2,p3;
            unpk2(acc[i][2*g],   p0, p1);
            unpk2(acc[i][2*g+1], p2, p3);
            p0 += bs[i]; p1 += bs[i]; p2 += bs[i]; p3 += bs[i];
            size_t off = ((size_t)(b*64 + rm + i))*NK + col0 + g*4;
            *(float4*)(g_G  + off) = make_float4(qv[i]-ka[0][i]+p0, qv[i]-ka[1][i]+p1,
                                                 qv[i]-ka[2][i]+p2, qv[i]-ka[3][i]+p3);
            *(float4*)(g_vr + off) = make_float4(va[0][i]+p0, va[1][i]+p1,
                                                 va[2][i]+p2, va[3][i]+p3);
        }
    }
}

// ---------------- fused fg1 + relu + fg2 (R9 shapes + register weight prefetch) ----------------
__global__ void __launch_bounds__(256) fgfused_kernel(const float* __restrict__ fg2_b)
{
    extern __shared__ __align__(16) float dynB[];
    float* sG = dynB;
    float* sH = dynB + 64*68;
    float* sW = dynB + 64*68 + 256*68;
    int tid = threadIdx.x;
    int b = blockIdx.z;
    int col0 = blockIdx.x * 64;

    #pragma unroll
    for (int i = 0; i < 4; i++) { int t = tid + i*256; int c = t>>4, f4 = (t&15)*4;
        *(float4*)&sG[c*68 + f4] = *(const float4*)(g_G + ((size_t)(b*64+c))*NK + col0 + f4); }

    // phase 1: H[256 x 64]; 8x8 tiles; weights prefetched to regs
    int tx = tid & 7, ty = tid >> 3;
    int rn = tx*8, rm = ty*8;
    int lk1 = tid >> 6, lm1 = (tid & 63) * 4;   // loader coords: 4 float4/thread
    uint64_t acc[8][4];
    #pragma unroll
    for (int i = 0; i < 8; i++)
        #pragma unroll
        for (int j = 0; j < 4; j++) acc[i][j] = 0ull;
    float4 wpre[4];
    #pragma unroll
    for (int i = 0; i < 4; i++)
        wpre[i] = *(const float4*)(g_w_fg1 + (size_t)(i*4 + lk1)*256 + lm1);
    for (int kc = 0; kc < 4; ++kc) {
        __syncthreads();
        #pragma unroll
        for (int i = 0; i < 4; i++)
            *(float4*)&sW[(i*4 + lk1)*256 + lm1] = wpre[i];
        __syncthreads();
        if (kc < 3) {
            #pragma unroll
            for (int i = 0; i < 4; i++)
                wpre[i] = *(const float4*)(g_w_fg1 + (size_t)((kc+1)*16 + i*4 + lk1)*256 + lm1);
        }
        #pragma unroll
        for (int k = 0; k < 16; ++k) {
            int kk = kc*16 + k;
            ulonglong2 b0 = *(const ulonglong2*)&sG[kk*68 + rn];
            ulonglong2 b1 = *(const ulonglong2*)&sG[kk*68 + rn + 4];
            float4 a0 = *(const float4*)&sW[k*256 + rm];
            float4 a1 = *(const float4*)&sW[k*256 + rm + 4];
            float av[8] = {a0.x,a0.y,a0.z,a0.w,a1.x,a1.y,a1.z,a1.w};
            #pragma unroll
            for (int i = 0; i < 8; i++) {
                uint64_t ap = pk2(av[i], av[i]);
                fma2(acc[i][0], ap, b0.x); fma2(acc[i][1], ap, b0.y);
                fma2(acc[i][2], ap, b1.x); fma2(acc[i][3], ap, b1.y);
            }
        }
    }
    #pragma unroll
    for (int i = 0; i < 8; i++) {
        int row = rm + i;
        float sc = g_fold[128 + row], bb2 = g_fold[384 + row];
        float v[8];
        #pragma unroll
        for (int j = 0; j < 4; j++) unpk2(acc[i][j], v[2*j], v[2*j+1]);
        #pragma unroll
        for (int j = 0; j < 8; j++) v[j] = fmaxf(v[j]*sc + bb2, 0.f);
        *(float4*)&sH[row*68 + rn]     = make_float4(v[0],v[1],v[2],v[3]);
        *(float4*)&sH[row*68 + rn + 4] = make_float4(v[4],v[5],v[6],v[7]);
    }

    // phase 2: at[64 x 64]; 4x4 tiles; weights prefetched to regs
    int tx2 = tid & 15, ty2 = tid >> 4;
    int rn2 = tx2*4, rm2 = ty2*4;
    int lk2 = tid >> 4, lm2 = (tid & 15) * 4;   // loader coords: 4 float4/thread
    uint64_t accB[4][2];
    #pragma unroll
    for (int i = 0; i < 4; i++) { accB[i][0] = 0ull; accB[i][1] = 0ull; }
    #pragma unroll
    for (int i = 0; i < 4; i++)
        wpre[i] = *(const float4*)(g_w_fg2 + (size_t)(i*16 + lk2)*64 + lm2);
    for (int kc2 = 0; kc2 < 4; ++kc2) {
        __syncthreads();
        #pragma unroll
        for (int i = 0; i < 4; i++)
            *(float4*)&sW[(i*16 + lk2)*64 + lm2] = wpre[i];
        __syncthreads();
        if (kc2 < 3) {
            #pragma unroll
            for (int i = 0; i < 4; i++)
                wpre[i] = *(const float4*)(g_w_fg2 + (size_t)((kc2+1)*64 + i*16 + lk2)*64 + lm2);
        }
        #pragma unroll 4
        for (int k = 0; k < 64; ++k) {
            int kk = kc2*64 + k;
            ulonglong2 b2 = *(const ulonglong2*)&sH[kk*68 + rn2];
            float4 a4 = *(const float4*)&sW[k*64 + rm2];
            float av[4] = {a4.x, a4.y, a4.z, a4.w};
            #pragma unroll
            for (int i = 0; i < 4; i++) {
                uint64_t ap = pk2(av[i], av[i]);
                fma2(accB[i][0], ap, b2.x); fma2(accB[i][1], ap, b2.y);
            }
        }
    }
    #pragma unroll
    for (int i = 0; i < 4; i++) {
        int row = rm2 + i;
        float bb = __ldg(fg2_b + row);
        float v0,v1,v2,v3;
        unpk2(accB[i][0], v0, v1);
        unpk2(accB[i][1], v2, v3);
        *(float4*)(g_at + ((size_t)(b*64+row))*NK + col0 + rn2) =
            make_float4(v0+bb, v1+bb, v2+bb, v3+bb);
    }
}

// ---------------- fused ConvT(4,1) + softmax (no-max, fast div) + weighted sum + identity ----------------
__global__ void __launch_bounds__(256) k4_kernel(const float* __restrict__ at_b,
                                                 float* __restrict__ res_out)
{
    __shared__ __align__(16) float s_a[64*16];
    __shared__ float s_v[16*64];
    __shared__ float s_s[16][8];
    __shared__ float s_out[256];
    int bn = blockIdx.x;
    int b = bn >> 11, n = bn & 2047;
    int tid = threadIdx.x;
    int o = tid & 63, r = tid >> 6;
    int lane = tid & 31, warp = tid >> 5;
    {
        int c = tid >> 2, fq = (tid & 3) * 4;
        size_t base = ((size_t)(b*64 + c)*2048 + n)*16 + fq;
        float4 a4 = *(const float4*)(g_at + base);
        *(float4*)(s_a + c*16 + fq) = a4;
        float4 v4 = *(const float4*)(g_vr + base);
        s_v[(fq+0)*64 + c] = v4.x;
        s_v[(fq+1)*64 + c] = v4.y;
        s_v[(fq+2)*64 + c] = v4.z;
        s_v[(fq+3)*64 + c] = v4.w;
    }
    __syncthreads();

    float bo = at_b[o];
    uint64_t y2[8];
    uint64_t bo2 = pk2(bo, bo);
    #pragma unroll
    for (int f = 0; f < 8; f++) y2[f] = bo2;
    const float* w = g_wT + r*4096 + o;
    #pragma unroll 4
    for (int c = 0; c < 64; c++) {
        uint64_t wp = pk2(w[c*64], w[c*64]);
        const ulonglong2* ap = (const ulonglong2*)(s_a + c*16);
        ulonglong2 q0 = ap[0], q1 = ap[1];
        fma2(y2[0], wp, q0.x); fma2(y2[1], wp, q0.y);
        fma2(y2[2], wp, q1.x); fma2(y2[3], wp, q1.y);
        ulonglong2 q2 = ap[2], q3 = ap[3];
        fma2(y2[4], wp, q2.x); fma2(y2[5], wp, q2.y);
        fma2(y2[6], wp, q3.x); fma2(y2[7], wp, q3.y);
    }
    float y[16];
    #pragma unroll
    for (int f = 0; f < 8; f++) unpk2(y2[f], y[2*f], y[2*f+1]);

    #pragma unroll
    for (int f = 0; f < 16; f++) {
        float e = __expf(y[f]);
        y[f] = e;
        float sm = e;
        #pragma unroll
        for (int off = 16; off; off >>= 1) sm += __shfl_xor_sync(0xffffffffu, sm, off);
        if (lane == 0) s_s[f][warp] = sm;
    }
    __syncthreads();
    float acc = 0.f;
    #pragma unroll
    for (int f = 0; f < 16; f++) {
        float sum = s_s[f][2*r] + s_s[f][2*r+1];
        acc = fmaf(__fdividef(y[f], sum), s_v[f*64 + o], acc);
    }
    acc += g_x[(size_t)b*131072 + o*2048 + n];
    s_out[o*4 + r] = acc;
    __syncthreads();
    if (tid < 64) {
        float4 ov = *(const float4*)(s_out + tid*4);
        *(float4*)(res_out + (size_t)b*524288 + (size_t)tid*8192 + n*4) = ov;
    }
}

// ---------------- fused m41 + relu + m42 ----------------
__global__ void __launch_bounds__(128) m4_kernel(const float* __restrict__ res,
                                                 const float* __restrict__ m41_b,
                                                 const float* __restrict__ m42_w,
                                                 const float* __restrict__ m42_b,
                                                 float* __restrict__ out)
{
    extern __shared__ __align__(16) float dynD[];
    float* sWm  = dynD;
    float* sres = dynD + 64*68;
    float* sch  = dynD + 64*68 + 64*132;
    int tid = threadIdx.x;
    int b = blockIdx.z;
    int bn0 = blockIdx.x * 128;
    int tx = tid & 15, ty = tid >> 4;
    int rn = tx*8, rm = ty*8;

    #pragma unroll
    for (int i = 0; i < 8; i++) { int t = tid + i*128; int k = t>>4, m4 = (t&15)*4;
        *(float4*)&sWm[k*68 + m4] = *(const float4*)(g_w_m41 + k*64 + m4); }
    #pragma unroll
    for (int i = 0; i < 16; i++) { int t = tid + i*128; int k = t>>5, f = (t&31)*4;
        *(float4*)&sres[k*132 + f] = *(const float4*)(res + ((size_t)(b*64+k))*8192 + bn0 + f); }
    __syncthreads();

    uint64_t acc[8][4];
    #pragma unroll
    for (int i = 0; i < 8; i++)
        #pragma unroll
        for (int j = 0; j < 4; j++) acc[i][j] = 0ull;
    #pragma unroll 4
    for (int k = 0; k < 64; ++k) {
        ulonglong2 b0 = *(const ulonglong2*)&sres[k*132 + rn];
        ulonglong2 b1 = *(const ulonglong2*)&sres[k*132 + rn + 4];
        float4 a0 = *(const float4*)&sWm[k*68 + rm];
        float4 a1 = *(const float4*)&sWm[k*68 + rm + 4];
        float av[8] = {a0.x,a0.y,a0.z,a0.w,a1.x,a1.y,a1.z,a1.w};
        #pragma unroll
        for (int i = 0; i < 8; i++) {
            uint64_t ap = pk2(av[i], av[i]);
            fma2(acc[i][0], ap, b0.x); fma2(acc[i][1], ap, b0.y);
            fma2(acc[i][2], ap, b1.x); fma2(acc[i][3], ap, b1.y);
        }
    }
    #pragma unroll
    for (int i = 0; i < 8; i++) {
        int row = rm + i;
        float bs = m41_b[row];
        float v[8];
        #pragma unroll
        for (int j = 0; j < 4; j++) unpk2(acc[i][j], v[2*j], v[2*j+1]);
        #pragma unroll
        for (int j = 0; j < 8; j++) sch[row*132 + rn + j] = fmaxf(v[j] + bs, 0.f);
    }
    __syncthreads();
    if (tid < 48) *(float4*)&sWm[tid*4] = *(const float4*)(m42_w + tid*4);
    __syncthreads();

    float a0 = m42_b[0], a1 = m42_b[1], a2 = m42_b[2];
    #pragma unroll 8
    for (int k = 0; k < 64; ++k) {
        float xv = sch[k*132 + tid];
        a0 = fmaf(sWm[k],     xv, a0);
        a1 = fmaf(sWm[64+k],  xv, a1);
        a2 = fmaf(sWm[128+k], xv, a2);
    }
    out[(size_t)(b*3+0)*8192 + bn0 + tid] = a0;
    out[(size_t)(b*3+1)*8192 + bn0 + tid] = a1;
    out[(size_t)(b*3+2)*8192 + bn0 + tid] = a2;
}

// ---------------- launch ----------------
extern "C" void kernel_launch(void* const* d_in, const int* in_sizes, int n_in,
                              void* d_out, int out_size)
{
    const float* feature = (const float*)d_in[0];
    const float* xyz     = (const float*)d_in[1];
    const float* bt1_w = (const float*)d_in[2];  const float* bt1_b = (const float*)d_in[3];
    const float* bt2_w = (const float*)d_in[4];  const float* bt2_b = (const float*)d_in[5];
    const float* bts_w = (const float*)d_in[6];  const float* bts_b = (const float*)d_in[7];
    const float* q_w   = (const float*)d_in[8];  const float* q_b   = (const float*)d_in[9];
    const float* k_w   = (const float*)d_in[10]; const float* k_b   = (const float*)d_in[11];
    const float* v_w   = (const float*)d_in[12]; const float* v_b   = (const float*)d_in[13];
    const float* fd1_w = (const float*)d_in[14]; const float* fd1_b = (const float*)d_in[15];
    const float* fd_g  = (const float*)d_in[16]; const float* fd_bb = (const float*)d_in[17];
    const float* fd2_w = (const float*)d_in[18]; const float* fd2_b = (const float*)d_in[19];
    const float* fg1_w = (const float*)d_in[20]; const float* fg1_b = (const float*)d_in[21];
    const float* fg_g  = (const float*)d_in[22]; const float* fg_bb = (const float*)d_in[23];
    const float* fg2_w = (const float*)d_in[24]; const float* fg2_b = (const float*)d_in[25];
    const float* at_w  = (const float*)d_in[26]; const float* at_b  = (const float*)d_in[27];
    const float* m41_w = (const float*)d_in[28]; const float* m41_b = (const float*)d_in[29];
    const float* m42_w = (const float*)d_in[30]; const float* m42_b = (const float*)d_in[31];

    float* out = (float*)d_out;
    float* res = out + BB*3*4*NN;

    const int smemA = (64*68 + 64*132 + 256) * 4;      // 52224
    const int smemB = (64*68 + 256*68 + 4096) * 4;     // 103424
    const int smemD = (64*68 + 64*132 + 64*132) * 4;   // 84992
    static bool attr_done = false;
    if (!attr_done) {
        cudaFuncSetAttribute(fd2gv_kernel,   cudaFuncAttributeMaxDynamicSharedMemorySize, smemA);
        cudaFuncSetAttribute(fgfused_kernel, cudaFuncAttributeMaxDynamicSharedMemorySize, smemB);
        cudaFuncSetAttribute(m4_kernel,      cudaFuncAttributeMaxDynamicSharedMemorySize, smemD);
        attr_done = true;
    }

    prep_kernel<<<256, 256>>>(fd_g, fd1_b, fd_bb, fg_g, fg1_b, fg_bb, at_w, fd1_w,
                              bt1_w, bt1_b, bts_w, bts_b,
                              fd2_w, fg1_w, fg2_w, m41_w);
    prep2_kernel<<<130, 256>>>(bt2_w, bt2_b, q_w, q_b, k_w, k_b, v_w, v_b);
    knn_kernel<<<BB*NN/16, 512>>>(xyz);

    bt1s_kernel<<<dim3(32,4,BB), 128>>>(feature);
    xqkv_kernel<<<dim3(16,4,BB), 128>>>();

    fd2gv_kernel<<<dim3(256,1,BB), 128, smemA>>>(xyz, fd2_b);

    fgfused_kernel<<<dim3(512,1,BB), 256, smemB>>>(fg2_b);

    k4_kernel<<<BB*NN, 256>>>(at_b, res);

    m4_kernel<<<dim3(64,1,BB), 128, smemD>>>(res, m41_b, m42_w, m42_b, out);
}

// round 15
// speedup vs baseline: 1.0155x; 1.0155x over previous
#include <cuda_runtime.h>
#include <cstdint>

#define BB 4
#define NN 2048
#define KK 16
#define DD 64
#define NK (NN*KK)
#define EPSV 1e-5f

// ---------------- f32x2 packed FMA helpers ----------------
__device__ __forceinline__ uint64_t pk2(float lo, float hi){
    uint64_t r;
    asm("mov.b64 %0, {%1, %2};" : "=l"(r) : "r"(__float_as_uint(lo)), "r"(__float_as_uint(hi)));
    return r;
}
__device__ __forceinline__ void fma2(uint64_t& d, uint64_t a, uint64_t b){
    asm("fma.rn.f32x2 %0, %1, %2, %0;" : "+l"(d) : "l"(a), "l"(b));
}
__device__ __forceinline__ void unpk2(uint64_t v, float& lo, float& hi){
    uint32_t l, h;
    asm("mov.b64 {%0, %1}, %2;" : "=r"(l), "=r"(h) : "l"(v));
    lo = __uint_as_float(l); hi = __uint_as_float(h);
}

// ---------------- scratch ----------------
__device__ float g_hx  [BB*128*NN];
__device__ float g_p1  [BB*128*NN];
__device__ float g_p2  [BB*128*NN];
__device__ float g_p3  [BB*128*NN];
__device__ float g_x   [BB*DD*NN];
__device__ float g_qkvt[BB*NN*192];
__device__ int   g_idx [BB*KK*NN];
__device__ float g_G   [BB*DD*NK];
__device__ float g_vr  [BB*DD*NK];
__device__ float g_at  [BB*DD*NK];
__device__ float g_fold[640];
__device__ float g_fd1f[256];
__device__ float g_wT  [4*64*64];
__device__ float g_w_bt1s[480*128];
__device__ float g_b_bt1s[128];
__device__ float g_w_xqkv[128*256];
__device__ float g_b_xqkv[256];
__device__ float g_w_fd2 [64*64];
__device__ float g_w_fg1 [64*256];
__device__ float g_w_fg2 [256*64];
__device__ float g_w_m41 [64*64];

// ---------------- prep ----------------
__global__ void prep_kernel(const float* __restrict__ fd_g, const float* __restrict__ fd1_b,
                            const float* __restrict__ fd_bb,
                            const float* __restrict__ fg_g, const float* __restrict__ fg1_b,
                            const float* __restrict__ fg_bb,
                            const float* __restrict__ at_w, const float* __restrict__ fd1_w,
                            const float* __restrict__ bt1_w, const float* __restrict__ bt1_b,
                            const float* __restrict__ bts_w, const float* __restrict__ bts_b,
                            const float* __restrict__ fd2_w,
                            const float* __restrict__ fg1_w, const float* __restrict__ fg2_w,
                            const float* __restrict__ m41_w)
{
    int t = blockIdx.x * blockDim.x + threadIdx.x;
    float inv = rsqrtf(1.f + EPSV);
    if (t < 64) {
        float s = fd_g[t]*inv;
        g_fd1f[t]       = fd1_w[t*3]   * s;
        g_fd1f[64+t]    = fd1_w[t*3+1] * s;
        g_fd1f[128+t]   = fd1_w[t*3+2] * s;
        g_fd1f[192+t]   = fd1_b[t]*s + fd_bb[t];
    }
    if (t < 256) { float s = fg_g[t]*inv; g_fold[128+t] = s; g_fold[384+t] = fg1_b[t]*s + fg_bb[t]; }
    if (t < 16384) {
        int r = t & 3, o = (t >> 2) & 63, c = t >> 8;
        g_wT[r*4096 + c*64 + o] = at_w[t];
        { int k = t >> 8, m = t & 255; g_w_fg1[k*256 + m] = fg1_w[m*64 + k]; }
        { int k = t >> 6, m = t & 63;  g_w_fg2[k*64 + m]  = fg2_w[m*256 + k]; }
    }
    if (t < 61440) { int k = t >> 7, m = t & 127;
        g_w_bt1s[t] = (m < 64) ? bt1_w[m*480 + k] : bts_w[(m-64)*480 + k]; }
    if (t < 128) g_b_bt1s[t] = (t < 64) ? bt1_b[t] : bts_b[t-64];
    if (t < 4096) { int k = t >> 6, m = t & 63;
        g_w_fd2[t] = fd2_w[m*64+k];
        g_w_m41[t] = m41_w[m*64+k]; }
}

// ---------------- prep2: composite x/qkv weights ----------------
__global__ void prep2_kernel(const float* __restrict__ bt2_w, const float* __restrict__ bt2_b,
                             const float* __restrict__ q_w, const float* __restrict__ q_b,
                             const float* __restrict__ k_w, const float* __restrict__ k_b,
                             const float* __restrict__ v_w, const float* __restrict__ v_b)
{
    int t = blockIdx.x * blockDim.x + threadIdx.x;
    if (t < 32768) {
        int m = t & 255, k = t >> 8;
        float val;
        if (k < 64) {
            if (m < 64) val = bt2_w[m*64 + k];
            else {
                int mm = m - 64;
                const float* wr = (mm < 64) ? q_w + mm*64
                                 : (mm < 128 ? k_w + (mm-64)*64 : v_w + (mm-128)*64);
                float s = 0.f;
                #pragma unroll 8
                for (int c = 0; c < 64; c++) s += wr[c] * bt2_w[c*64 + k];
                val = s;
            }
        } else {
            int kk = k - 64;
            if (m < 64) val = (m == kk) ? 1.f : 0.f;
            else {
                int mm = m - 64;
                val = (mm < 64) ? q_w[mm*64 + kk]
                     : (mm < 128 ? k_w[(mm-64)*64 + kk] : v_w[(mm-128)*64 + kk]);
            }
        }
        g_w_xqkv[k*256 + m] = val;
    } else if (t < 33024) {
        int m = t - 32768;
        if (m < 64) g_b_xqkv[m] = bt2_b[m];
        else {
            int mm = m - 64;
            const float* wr = (mm < 64) ? q_w + mm*64
                             : (mm < 128 ? k_w + (mm-64)*64 : v_w + (mm-128)*64);
            float s = (mm < 64) ? q_b[mm] : (mm < 128 ? k_b[mm-64] : v_b[mm-128]);
            #pragma unroll 8
            for (int c = 0; c < 64; c++) s += wr[c] * bt2_b[c];
            g_b_xqkv[m] = s;
        }
    }
}

// ---------------- KNN ----------------
__global__ void knn_kernel(const float* __restrict__ xyz)
{
    __shared__ float sx[NN], sy[NN], sz[NN], ssq[NN];
    int b  = blockIdx.x >> 7;
    int n0 = (blockIdx.x & 127) * 16;
    const float* xb = xyz + b*3*NN;
    for (int m = threadIdx.x; m < NN; m += blockDim.x) {
        float px = xb[m], py = xb[NN+m], pz = xb[2*NN+m];
        sx[m]=px; sy[m]=py; sz[m]=pz; ssq[m] = px*px + py*py + pz*pz;
    }
    __syncthreads();
    int warp = threadIdx.x >> 5, lane = threadIdx.x & 31;
    int n = n0 + warp;
    float px = sx[n], py = sy[n], pz = sz[n], sqn = ssq[n];

    float bv[17]; int bi[17];
    #pragma unroll
    for (int i = 0; i < 17; i++) { bv[i] = 3.4e38f; bi[i] = 0x7fffffff; }
    for (int m = lane; m < NN; m += 32) {
        float d2 = sqn + ssq[m] - 2.f*(px*sx[m] + py*sy[m] + pz*sz[m]);
        if (d2 < bv[16]) {
            bv[16] = d2; bi[16] = m;
            #pragma unroll
            for (int s = 16; s > 0; --s)
                if (bv[s] < bv[s-1]) {
                    float tv = bv[s]; bv[s] = bv[s-1]; bv[s-1] = tv;
                    int   ti = bi[s]; bi[s] = bi[s-1]; bi[s-1] = ti;
                }
        }
    }
    for (int t = 0; t < 17; ++t) {
        float hv = bv[0]; int hi = bi[0];
        float v = hv; int id = hi;
        #pragma unroll
        for (int off = 16; off; off >>= 1) {
            float ov = __shfl_xor_sync(0xffffffffu, v, off);
            int   oi = __shfl_xor_sync(0xffffffffu, id, off);
            if (ov < v || (ov == v && oi < id)) { v = ov; id = oi; }
        }
        if (t > 0 && lane == 0) g_idx[b*KK*NN + (t-1)*NN + n] = id;
        if (hv == v && hi == id) {
            #pragma unroll
            for (int s = 0; s < 16; ++s) { bv[s] = bv[s+1]; bi[s] = bi[s+1]; }
            bv[16] = 3.4e38f; bi[16] = 0x7fffffff;
        }
    }
}

// ---------------- bt1s split-K(4) GEMM ----------------
__global__ void __launch_bounds__(128) bt1s_kernel(const float* __restrict__ feature)
{
    constexpr int KC = 8;
    __shared__ __align__(16) float sW[2][KC][128];
    __shared__ __align__(16) float sX[2][KC][64];
    int tid = threadIdx.x;
    int b = blockIdx.z;
    int split = blockIdx.y;
    int bn0 = blockIdx.x * 64;
    const float* Wt = g_w_bt1s + (size_t)split*120*128;
    const float* Xb = feature + (size_t)b*480*NN + (size_t)split*120*NN;
    float* Cb = (split == 0 ? g_hx : (split == 1 ? g_p1 : (split == 2 ? g_p2 : g_p3)))
                + (size_t)b*128*NN;

    float4 wr[2], xr1;
    uint64_t acc2[8][4];
    #pragma unroll
    for (int i = 0; i < 8; i++)
        #pragma unroll
        for (int j = 0; j < 4; j++) acc2[i][j] = 0ull;
    int tx = tid & 7, ty = tid >> 3;
    int rm = ty*8, rn = tx*8;

    {
        #pragma unroll
        for (int i = 0; i < 2; i++) { int t = tid + i*128; int k = t>>5, m4 = (t&31)*4;
            wr[i] = *(const float4*)(Wt + (size_t)k*128 + m4); }
        { int k = tid >> 4, n4 = (tid & 15)*4;
          xr1 = *(const float4*)(Xb + (size_t)k*NN + bn0 + n4); }
        #pragma unroll
        for (int i = 0; i < 2; i++) { int t = tid + i*128; int k = t>>5, m4 = (t&31)*4;
            *(float4*)&sW[0][k][m4] = wr[i]; }
        { int k = tid >> 4, n4 = (tid & 15)*4; *(float4*)&sX[0][k][n4] = xr1; }
    }
    __syncthreads();

    for (int c = 0; c < 15; ++c) {
        if (c + 1 < 15) {
            int k0 = (c+1)*KC;
            #pragma unroll
            for (int i = 0; i < 2; i++) { int t = tid + i*128; int k = t>>5, m4 = (t&31)*4;
                wr[i] = *(const float4*)(Wt + (size_t)(k0+k)*128 + m4); }
            { int k = tid >> 4, n4 = (tid & 15)*4;
              xr1 = *(const float4*)(Xb + (size_t)(k0 + (tid>>4))*NN + bn0 + n4); }
        }
        int buf = c & 1;
        #pragma unroll
        for (int k = 0; k < KC; ++k) {
            ulonglong2 bq0 = *(const ulonglong2*)&sX[buf][k][rn];
            ulonglong2 bq1 = *(const ulonglong2*)&sX[buf][k][rn+4];
            uint64_t bp[4] = {bq0.x, bq0.y, bq1.x, bq1.y};
            float4 a0 = *(const float4*)&sW[buf][k][rm];
            float4 a1 = *(const float4*)&sW[buf][k][rm+4];
            float av[8] = {a0.x,a0.y,a0.z,a0.w,a1.x,a1.y,a1.z,a1.w};
            #pragma unroll
            for (int i = 0; i < 8; i++) {
                uint64_t ap = pk2(av[i], av[i]);
                #pragma unroll
                for (int j = 0; j < 4; j++) fma2(acc2[i][j], ap, bp[j]);
            }
        }
        if (c + 1 < 15) {
            int nb = (c+1) & 1;
            #pragma unroll
            for (int i = 0; i < 2; i++) { int t = tid + i*128; int k = t>>5, m4 = (t&31)*4;
                *(float4*)&sW[nb][k][m4] = wr[i]; }
            { int k = tid >> 4, n4 = (tid & 15)*4; *(float4*)&sX[nb][k][n4] = xr1; }
        }
        __syncthreads();
    }

    #pragma unroll
    for (int i = 0; i < 8; i++) {
        int row = rm + i;
        float v[8];
        #pragma unroll
        for (int j = 0; j < 4; j++) unpk2(acc2[i][j], v[2*j], v[2*j+1]);
        *(float4*)(Cb + (size_t)row*NN + bn0 + rn)     = make_float4(v[0],v[1],v[2],v[3]);
        *(float4*)(Cb + (size_t)row*NN + bn0 + rn + 4) = make_float4(v[4],v[5],v[6],v[7]);
    }
}

__device__ __forceinline__ float4 hx_load(const float* p0, const float* p1,
                                          const float* p2, const float* p3,
                                          size_t off, int kglob)
{
    float4 a = *(const float4*)(p0 + off);
    float4 c = *(const float4*)(p1 + off);
    float4 d = *(const float4*)(p2 + off);
    float4 e = *(const float4*)(p3 + off);
    float bs = g_b_bt1s[kglob];
    float4 r = make_float4(a.x+c.x+d.x+e.x+bs, a.y+c.y+d.y+e.y+bs,
                           a.z+c.z+d.z+e.z+bs, a.w+c.w+d.w+e.w+bs);
    if (kglob < 64) {
        r.x = fmaxf(r.x, 0.f); r.y = fmaxf(r.y, 0.f);
        r.z = fmaxf(r.z, 0.f); r.w = fmaxf(r.w, 0.f);
    }
    return r;
}

// ---------------- xqkv ----------------
__global__ void __launch_bounds__(128) xqkv_kernel()
{
    constexpr int KC = 8;
    __shared__ __align__(16) float sW[2][KC][64];
    __shared__ __align__(16) float sX[2][KC][128];
    int tid = threadIdx.x;
    int b = blockIdx.z;
    int bn0 = blockIdx.x * 128;
    int bm0 = blockIdx.y * 64;
    const float* p0 = g_hx + (size_t)b * 128 * NN;
    const float* p1 = g_p1 + (size_t)b * 128 * NN;
    const float* p2 = g_p2 + (size_t)b * 128 * NN;
    const float* p3 = g_p3 + (size_t)b * 128 * NN;

    float4 wr1, xr[2];
    uint64_t acc2[8][4];
    #pragma unroll
    for (int i = 0; i < 8; i++)
        #pragma unroll
        for (int j = 0; j < 4; j++) acc2[i][j] = 0ull;
    int tx = tid & 15, ty = tid >> 4;
    int rm = ty*8, rn = tx*8;
    int wk = tid >> 4;
    int wm = (tid & 15) * 4;

    {
        wr1 = *(const float4*)(g_w_xqkv + (size_t)wk*256 + bm0 + wm);
        #pragma unroll
        for (int i = 0; i < 2; i++) { int t = tid + i*128; int k = t >> 5, n4 = t & 31;
            xr[i] = hx_load(p0, p1, p2, p3, (size_t)k*NN + bn0 + n4*4, k); }
        *(float4*)&sW[0][wk][wm] = wr1;
        #pragma unroll
        for (int i = 0; i < 2; i++) { int t = tid + i*128; int k = t >> 5, n4 = t & 31;
            *(float4*)&sX[0][k][n4*4] = xr[i]; }
    }
    __syncthreads();

    for (int c = 0; c < 16; ++c) {
        if (c + 1 < 16) {
            int k0 = (c+1)*KC;
            wr1 = *(const float4*)(g_w_xqkv + (size_t)(k0+wk)*256 + bm0 + wm);
            #pragma unroll
            for (int i = 0; i < 2; i++) { int t = tid + i*128; int k = t >> 5, n4 = t & 31;
                xr[i] = hx_load(p0, p1, p2, p3, (size_t)(k0+k)*NN + bn0 + n4*4, k0+k); }
        }
        int buf = c & 1;
        #pragma unroll
        for (int k = 0; k < KC; ++k) {
            ulonglong2 bq0 = *(const ulonglong2*)&sX[buf][k][rn];
            ulonglong2 bq1 = *(const ulonglong2*)&sX[buf][k][rn+4];
            uint64_t bp[4] = {bq0.x, bq0.y, bq1.x, bq1.y};
            float4 a0 = *(const float4*)&sW[buf][k][rm];
            float4 a1 = *(const float4*)&sW[buf][k][rm+4];
            float av[8] = {a0.x,a0.y,a0.z,a0.w,a1.x,a1.y,a1.z,a1.w};
            #pragma unroll
            for (int i = 0; i < 8; i++) {
                uint64_t ap = pk2(av[i], av[i]);
                #pragma unroll
                for (int j = 0; j < 4; j++) fma2(acc2[i][j], ap, bp[j]);
            }
        }
        if (c + 1 < 16) {
            int nb = (c+1) & 1;
            *(float4*)&sW[nb][wk][wm] = wr1;
            #pragma unroll
            for (int i = 0; i < 2; i++) { int t = tid + i*128; int k = t >> 5, n4 = t & 31;
                *(float4*)&sX[nb][k][n4*4] = xr[i]; }
        }
        __syncthreads();
    }

    float v[8][8];
    #pragma unroll
    for (int i = 0; i < 8; i++) {
        float bs = g_b_xqkv[bm0 + rm + i];
        #pragma unroll
        for (int j = 0; j < 4; j++) {
            float lo, hi;
            unpk2(acc2[i][j], lo, hi);
            v[i][2*j] = lo + bs; v[i][2*j+1] = hi + bs;
        }
    }
    if (blockIdx.y == 0) {
        #pragma unroll
        for (int i = 0; i < 8; i++) {
            int row = rm + i;
            *(float4*)(g_x + ((size_t)(b*64+row))*NN + bn0 + rn)
                = make_float4(v[i][0],v[i][1],v[i][2],v[i][3]);
            *(float4*)(g_x + ((size_t)(b*64+row))*NN + bn0 + rn + 4)
                = make_float4(v[i][4],v[i][5],v[i][6],v[i][7]);
        }
    } else {
        int qbase = bm0 + rm - 64;
        #pragma unroll
        for (int j = 0; j < 8; j++) {
            int n = bn0 + rn + j;
            float* dst = g_qkvt + ((size_t)(b*NN) + n)*192 + qbase;
            *(float4*)dst       = make_float4(v[0][j],v[1][j],v[2][j],v[3][j]);
            *(float4*)(dst + 4) = make_float4(v[4][j],v[5][j],v[6][j],v[7][j]);
        }
    }
}

// ---------------- fused posenc(fd1) + fd2 GEMM + G/Vrel build ----------------
__global__ void __launch_bounds__(128) fd2gv_kernel(const float* __restrict__ xyz,
                                                    const float* __restrict__ fd2_b)
{
    extern __shared__ __align__(16) float dynA[];
    float* sW = dynA;
    float* sT = dynA + 64*68;
    float* sF = dynA + 64*68 + 64*132;
    int tid = threadIdx.x;
    int b = blockIdx.z;
    int bn0 = blockIdx.x * 128;
    int tx = tid & 15, ty = tid >> 4;
    int rn = tx*8, rm = ty*8;

    #pragma unroll
    for (int i = 0; i < 8; i++) { int t = tid + i*128; int k = t>>4, m4 = (t&15)*4;
        *(float4*)&sW[k*68 + m4] = *(const float4*)(g_w_fd2 + k*64 + m4); }
    sF[tid] = g_fd1f[tid];
    sF[tid+128] = g_fd1f[tid+128];

    int col = bn0 + tid;
    int np = col >> 4, jp = col & 15;
    int idg = g_idx[b*KK*NN + jp*NN + np];
    const float* xb = xyz + b*3*NN;
    float rx = xb[np]      - xb[idg];
    float ry = xb[NN+np]   - xb[NN+idg];
    float rz = xb[2*NN+np] - xb[2*NN+idg];
    __syncthreads();
    #pragma unroll 8
    for (int m = 0; m < 64; ++m) {
        float v = sF[m]*rx + sF[64+m]*ry + sF[128+m]*rz + sF[192+m];
        sT[m*132 + tid] = fmaxf(v, 0.f);
    }
    __syncthreads();

    uint64_t acc[8][4];
    #pragma unroll
    for (int i = 0; i < 8; i++)
        #pragma unroll
        for (int j = 0; j < 4; j++) acc[i][j] = 0ull;
    #pragma unroll 4
    for (int k = 0; k < 64; ++k) {
        ulonglong2 b0 = *(const ulonglong2*)&sT[k*132 + rn];
        ulonglong2 b1 = *(const ulonglong2*)&sT[k*132 + rn + 4];
        float4 a0 = *(const float4*)&sW[k*68 + rm];
        float4 a1 = *(const float4*)&sW[k*68 + rm + 4];
        float av[8] = {a0.x,a0.y,a0.z,a0.w,a1.x,a1.y,a1.z,a1.w};
        #pragma unroll
        for (int i = 0; i < 8; i++) {
            uint64_t ap = pk2(av[i], av[i]);
            fma2(acc[i][0], ap, b0.x); fma2(acc[i][1], ap, b0.y);
            fma2(acc[i][2], ap, b1.x); fma2(acc[i][3], ap, b1.y);
        }
    }

    int col0 = bn0 + rn;
    int n = col0 >> 4, j0 = col0 & 15;
    float qv[8], bs[8];
    const float* qp = g_qkvt + ((size_t)b*NN + n)*192 + rm;
    *(float4*)&qv[0] = *(const float4*)qp;
    *(float4*)&qv[4] = *(const float4*)(qp + 4);
    #pragma unroll
    for (int i = 0; i < 8; i++) bs[i] = fd2_b[rm + i];

    #pragma unroll
    for (int g = 0; g < 2; ++g) {
        float ka[4][8], va[4][8];
        #pragma unroll
        for (int jj = 0; jj < 4; jj++) {
            int id = g_idx[b*KK*NN + (j0 + g*4 + jj)*NN + n];
            const float* kp = g_qkvt + ((size_t)b*NN + id)*192 + 64 + rm;
            *(float4*)&ka[jj][0] = *(const float4*)kp;
            *(float4*)&ka[jj][4] = *(const float4*)(kp + 4);
            *(float4*)&va[jj][0] = *(const float4*)(kp + 64);
            *(float4*)&va[jj][4] = *(const float4*)(kp + 68);
        }
        #pragma unroll
        for (int i = 0; i < 8; i++) {
            float p0,p1,p2,p3;
            unpk2(acc[i][2*g],   p0, p1);
            unpk2(acc[i][2*g+1], p2, p3);
            p0 += bs[i]; p1 += bs[i]; p2 += bs[i]; p3 += bs[i];
            size_t off = ((size_t)(b*64 + rm + i))*NK + col0 + g*4;
            *(float4*)(g_G  + off) = make_float4(qv[i]-ka[0][i]+p0, qv[i]-ka[1][i]+p1,
                                                 qv[i]-ka[2][i]+p2, qv[i]-ka[3][i]+p3);
            *(float4*)(g_vr + off) = make_float4(va[0][i]+p0, va[1][i]+p1,
                                                 va[2][i]+p2, va[3][i]+p3);
        }
    }
}

// ---------------- fused fg1 + relu + fg2 ----------------
__global__ void __launch_bounds__(256) fgfused_kernel(const float* __restrict__ fg2_b)
{
    extern __shared__ __align__(16) float dynB[];
    float* sG = dynB;
    float* sH = dynB + 64*68;
    float* sW = dynB + 64*68 + 256*68;
    int tid = threadIdx.x;
    int b = blockIdx.z;
    int col0 = blockIdx.x * 64;

    #pragma unroll
    for (int i = 0; i < 4; i++) { int t = tid + i*256; int c = t>>4, f4 = (t&15)*4;
        *(float4*)&sG[c*68 + f4] = *(const float4*)(g_G + ((size_t)(b*64+c))*NK + col0 + f4); }

    // phase 1: H[256 x 64]; 8x8 tiles
    int tx = tid & 7, ty = tid >> 3;
    int rn = tx*8, rm = ty*8;
    int lk1 = tid >> 6, lm1 = (tid & 63) * 4;
    uint64_t acc[8][4];
    #pragma unroll
    for (int i = 0; i < 8; i++)
        #pragma unroll
        for (int j = 0; j < 4; j++) acc[i][j] = 0ull;
    float4 wpre[4];
    #pragma unroll
    for (int i = 0; i < 4; i++)
        wpre[i] = *(const float4*)(g_w_fg1 + (size_t)(i*4 + lk1)*256 + lm1);
    for (int kc = 0; kc < 4; ++kc) {
        __syncthreads();
        #pragma unroll
        for (int i = 0; i < 4; i++)
            *(float4*)&sW[(i*4 + lk1)*256 + lm1] = wpre[i];
        __syncthreads();
        if (kc < 3) {
            #pragma unroll
            for (int i = 0; i < 4; i++)
                wpre[i] = *(const float4*)(g_w_fg1 + (size_t)((kc+1)*16 + i*4 + lk1)*256 + lm1);
        }
        #pragma unroll
        for (int k = 0; k < 16; ++k) {
            int kk = kc*16 + k;
            ulonglong2 b0 = *(const ulonglong2*)&sG[kk*68 + rn];
            ulonglong2 b1 = *(const ulonglong2*)&sG[kk*68 + rn + 4];
            float4 a0 = *(const float4*)&sW[k*256 + rm];
            float4 a1 = *(const float4*)&sW[k*256 + rm + 4];
            float av[8] = {a0.x,a0.y,a0.z,a0.w,a1.x,a1.y,a1.z,a1.w};
            #pragma unroll
            for (int i = 0; i < 8; i++) {
                uint64_t ap = pk2(av[i], av[i]);
                fma2(acc[i][0], ap, b0.x); fma2(acc[i][1], ap, b0.y);
                fma2(acc[i][2], ap, b1.x); fma2(acc[i][3], ap, b1.y);
            }
        }
    }
    #pragma unroll
    for (int i = 0; i < 8; i++) {
        int row = rm + i;
        float sc = g_fold[128 + row], bb2 = g_fold[384 + row];
        float v[8];
        #pragma unroll
        for (int j = 0; j < 4; j++) unpk2(acc[i][j], v[2*j], v[2*j+1]);
        #pragma unroll
        for (int j = 0; j < 8; j++) v[j] = fmaxf(v[j]*sc + bb2, 0.f);
        *(float4*)&sH[row*68 + rn]     = make_float4(v[0],v[1],v[2],v[3]);
        *(float4*)&sH[row*68 + rn + 4] = make_float4(v[4],v[5],v[6],v[7]);
    }

    // phase 2: at[64 x 64]; 4x4 tiles
    int tx2 = tid & 15, ty2 = tid >> 4;
    int rn2 = tx2*4, rm2 = ty2*4;
    int lk2 = tid >> 4, lm2 = (tid & 15) * 4;
    uint64_t accB[4][2];
    #pragma unroll
    for (int i = 0; i < 4; i++) { accB[i][0] = 0ull; accB[i][1] = 0ull; }
    #pragma unroll
    for (int i = 0; i < 4; i++)
        wpre[i] = *(const float4*)(g_w_fg2 + (size_t)(i*16 + lk2)*64 + lm2);
    for (int kc2 = 0; kc2 < 4; ++kc2) {
        __syncthreads();
        #pragma unroll
        for (int i = 0; i < 4; i++)
            *(float4*)&sW[(i*16 + lk2)*64 + lm2] = wpre[i];
        __syncthreads();
        if (kc2 < 3) {
            #pragma unroll
            for (int i = 0; i < 4; i++)
                wpre[i] = *(const float4*)(g_w_fg2 + (size_t)((kc2+1)*64 + i*16 + lk2)*64 + lm2);
        }
        #pragma unroll 4
        for (int k = 0; k < 64; ++k) {
            int kk = kc2*64 + k;
            ulonglong2 b2 = *(const ulonglong2*)&sH[kk*68 + rn2];
            float4 a4 = *(const float4*)&sW[k*64 + rm2];
            float av[4] = {a4.x, a4.y, a4.z, a4.w};
            #pragma unroll
            for (int i = 0; i < 4; i++) {
                uint64_t ap = pk2(av[i], av[i]);
                fma2(accB[i][0], ap, b2.x); fma2(accB[i][1], ap, b2.y);
            }
        }
    }
    #pragma unroll
    for (int i = 0; i < 4; i++) {
        int row = rm2 + i;
        float bb = __ldg(fg2_b + row);
        float v0,v1,v2,v3;
        unpk2(accB[i][0], v0, v1);
        unpk2(accB[i][1], v2, v3);
        *(float4*)(g_at + ((size_t)(b*64+row))*NK + col0 + rn2) =
            make_float4(v0+bb, v1+bb, v2+bb, v3+bb);
    }
}

// ---------------- fused ConvT(4,1) + softmax + weighted sum + identity ----------------
__global__ void __launch_bounds__(256) k4_kernel(const float* __restrict__ at_b,
                                                 float* __restrict__ res_out)
{
    __shared__ __align__(16) float s_a[64*16];
    __shared__ float s_v[16*64];
    __shared__ float s_s[16][8];
    __shared__ float s_out[256];
    int bn = blockIdx.x;
    int b = bn >> 11, n = bn & 2047;
    int tid = threadIdx.x;
    int o = tid & 63, r = tid >> 6;
    int lane = tid & 31, warp = tid >> 5;
    {
        int c = tid >> 2, fq = (tid & 3) * 4;
        size_t base = ((size_t)(b*64 + c)*2048 + n)*16 + fq;
        float4 a4 = *(const float4*)(g_at + base);
        *(float4*)(s_a + c*16 + fq) = a4;
        float4 v4 = *(const float4*)(g_vr + base);
        s_v[(fq+0)*64 + c] = v4.x;
        s_v[(fq+1)*64 + c] = v4.y;
        s_v[(fq+2)*64 + c] = v4.z;
        s_v[(fq+3)*64 + c] = v4.w;
    }
    __syncthreads();

    float bo = at_b[o];
    uint64_t y2[8];
    uint64_t bo2 = pk2(bo, bo);
    #pragma unroll
    for (int f = 0; f < 8; f++) y2[f] = bo2;
    const float* w = g_wT + r*4096 + o;
    #pragma unroll 4
    for (int c = 0; c < 64; c++) {
        uint64_t wp = pk2(w[c*64], w[c*64]);
        const ulonglong2* ap = (const ulonglong2*)(s_a + c*16);
        ulonglong2 q0 = ap[0], q1 = ap[1];
        fma2(y2[0], wp, q0.x); fma2(y2[1], wp, q0.y);
        fma2(y2[2], wp, q1.x); fma2(y2[3], wp, q1.y);
        ulonglong2 q2 = ap[2], q3 = ap[3];
        fma2(y2[4], wp, q2.x); fma2(y2[5], wp, q2.y);
        fma2(y2[6], wp, q3.x); fma2(y2[7], wp, q3.y);
    }
    float y[16];
    #pragma unroll
    for (int f = 0; f < 8; f++) unpk2(y2[f], y[2*f], y[2*f+1]);

    #pragma unroll
    for (int f = 0; f < 16; f++) {
        float e = __expf(y[f]);
        y[f] = e;
        float sm = e;
        #pragma unroll
        for (int off = 16; off; off >>= 1) sm += __shfl_xor_sync(0xffffffffu, sm, off);
        if (lane == 0) s_s[f][warp] = sm;
    }
    __syncthreads();
    float acc = 0.f;
    #pragma unroll
    for (int f = 0; f < 16; f++) {
        float sum = s_s[f][2*r] + s_s[f][2*r+1];
        acc = fmaf(__fdividef(y[f], sum), s_v[f*64 + o], acc);
    }
    acc += g_x[(size_t)b*131072 + o*2048 + n];
    s_out[o*4 + r] = acc;
    __syncthreads();
    if (tid < 64) {
        float4 ov = *(const float4*)(s_out + tid*4);
        *(float4*)(res_out + (size_t)b*524288 + (size_t)tid*8192 + n*4) = ov;
    }
}

// ---------------- fused m41 + relu + m42 ----------------
__global__ void __launch_bounds__(128) m4_kernel(const float* __restrict__ res,
                                                 const float* __restrict__ m41_b,
                                                 const float* __restrict__ m42_w,
                                                 const float* __restrict__ m42_b,
                                                 float* __restrict__ out)
{
    extern __shared__ __align__(16) float dynD[];
    float* sWm  = dynD;
    float* sres = dynD + 64*68;
    float* sch  = dynD + 64*68 + 64*132;
    int tid = threadIdx.x;
    int b = blockIdx.z;
    int bn0 = blockIdx.x * 128;
    int tx = tid & 15, ty = tid >> 4;
    int rn = tx*8, rm = ty*8;

    #pragma unroll
    for (int i = 0; i < 8; i++) { int t = tid + i*128; int k = t>>4, m4 = (t&15)*4;
        *(float4*)&sWm[k*68 + m4] = *(const float4*)(g_w_m41 + k*64 + m4); }
    #pragma unroll
    for (int i = 0; i < 16; i++) { int t = tid + i*128; int k = t>>5, f = (t&31)*4;
        *(float4*)&sres[k*132 + f] = *(const float4*)(res + ((size_t)(b*64+k))*8192 + bn0 + f); }
    __syncthreads();

    uint64_t acc[8][4];
    #pragma unroll
    for (int i = 0; i < 8; i++)
        #pragma unroll
        for (int j = 0; j < 4; j++) acc[i][j] = 0ull;
    #pragma unroll 4
    for (int k = 0; k < 64; ++k) {
        ulonglong2 b0 = *(const ulonglong2*)&sres[k*132 + rn];
        ulonglong2 b1 = *(const ulonglong2*)&sres[k*132 + rn + 4];
        float4 a0 = *(const float4*)&sWm[k*68 + rm];
        float4 a1 = *(const float4*)&sWm[k*68 + rm + 4];
        float av[8] = {a0.x,a0.y,a0.z,a0.w,a1.x,a1.y,a1.z,a1.w};
        #pragma unroll
        for (int i = 0; i < 8; i++) {
            uint64_t ap = pk2(av[i], av[i]);
            fma2(acc[i][0], ap, b0.x); fma2(acc[i][1], ap, b0.y);
            fma2(acc[i][2], ap, b1.x); fma2(acc[i][3], ap, b1.y);
        }
    }
    #pragma unroll
    for (int i = 0; i < 8; i++) {
        int row = rm + i;
        float bs = m41_b[row];
        float v[8];
        #pragma unroll
        for (int j = 0; j < 4; j++) unpk2(acc[i][j], v[2*j], v[2*j+1]);
        #pragma unroll
        for (int j = 0; j < 8; j++) sch[row*132 + rn + j] = fmaxf(v[j] + bs, 0.f);
    }
    __syncthreads();
    if (tid < 48) *(float4*)&sWm[tid*4] = *(const float4*)(m42_w + tid*4);
    __syncthreads();

    float a0 = m42_b[0], a1 = m42_b[1], a2 = m42_b[2];
    #pragma unroll 8
    for (int k = 0; k < 64; ++k) {
        float xv = sch[k*132 + tid];
        a0 = fmaf(sWm[k],     xv, a0);
        a1 = fmaf(sWm[64+k],  xv, a1);
        a2 = fmaf(sWm[128+k], xv, a2);
    }
    out[(size_t)(b*3+0)*8192 + bn0 + tid] = a0;
    out[(size_t)(b*3+1)*8192 + bn0 + tid] = a1;
    out[(size_t)(b*3+2)*8192 + bn0 + tid] = a2;
}

// ---------------- launch (with stream fork: knn+prep2 overlap prep+bt1s) ----------------
extern "C" void kernel_launch(void* const* d_in, const int* in_sizes, int n_in,
                              void* d_out, int out_size)
{
    const float* feature = (const float*)d_in[0];
    const float* xyz     = (const float*)d_in[1];
    const float* bt1_w = (const float*)d_in[2];  const float* bt1_b = (const float*)d_in[3];
    const float* bt2_w = (const float*)d_in[4];  const float* bt2_b = (const float*)d_in[5];
    const float* bts_w = (const float*)d_in[6];  const float* bts_b = (const float*)d_in[7];
    const float* q_w   = (const float*)d_in[8];  const float* q_b   = (const float*)d_in[9];
    const float* k_w   = (const float*)d_in[10]; const float* k_b   = (const float*)d_in[11];
    const float* v_w   = (const float*)d_in[12]; const float* v_b   = (const float*)d_in[13];
    const float* fd1_w = (const float*)d_in[14]; const float* fd1_b = (const float*)d_in[15];
    const float* fd_g  = (const float*)d_in[16]; const float* fd_bb = (const float*)d_in[17];
    const float* fd2_w = (const float*)d_in[18]; const float* fd2_b = (const float*)d_in[19];
    const float* fg1_w = (const float*)d_in[20]; const float* fg1_b = (const float*)d_in[21];
    const float* fg_g  = (const float*)d_in[22]; const float* fg_bb = (const float*)d_in[23];
    const float* fg2_w = (const float*)d_in[24]; const float* fg2_b = (const float*)d_in[25];
    const float* at_w  = (const float*)d_in[26]; const float* at_b  = (const float*)d_in[27];
    const float* m41_w = (const float*)d_in[28]; const float* m41_b = (const float*)d_in[29];
    const float* m42_w = (const float*)d_in[30]; const float* m42_b = (const float*)d_in[31];

    float* out = (float*)d_out;
    float* res = out + BB*3*4*NN;

    const int smemA = (64*68 + 64*132 + 256) * 4;      // 52224
    const int smemB = (64*68 + 256*68 + 4096) * 4;     // 103424
    const int smemD = (64*68 + 64*132 + 64*132) * 4;   // 84992
    static bool attr_done = false;
    static cudaStream_t s2 = nullptr;
    static cudaEvent_t ev1 = nullptr, ev2 = nullptr;
    if (!attr_done) {
        cudaFuncSetAttribute(fd2gv_kernel,   cudaFuncAttributeMaxDynamicSharedMemorySize, smemA);
        cudaFuncSetAttribute(fgfused_kernel, cudaFuncAttributeMaxDynamicSharedMemorySize, smemB);
        cudaFuncSetAttribute(m4_kernel,      cudaFuncAttributeMaxDynamicSharedMemorySize, smemD);
        cudaStreamCreateWithFlags(&s2, cudaStreamNonBlocking);
        cudaEventCreateWithFlags(&ev1, cudaEventDisableTiming);
        cudaEventCreateWithFlags(&ev2, cudaEventDisableTiming);
        attr_done = true;
    }

    // Fork: side stream runs prep2 + knn while main stream runs prep + bt1s.
    cudaEventRecord(ev1, 0);
    cudaStreamWaitEvent(s2, ev1, 0);
    prep2_kernel<<<130, 256, 0, s2>>>(bt2_w, bt2_b, q_w, q_b, k_w, k_b, v_w, v_b);
    knn_kernel<<<BB*NN/16, 512, 0, s2>>>(xyz);
    cudaEventRecord(ev2, s2);

    prep_kernel<<<256, 256>>>(fd_g, fd1_b, fd_bb, fg_g, fg1_b, fg_bb, at_w, fd1_w,
                              bt1_w, bt1_b, bts_w, bts_b,
                              fd2_w, fg1_w, fg2_w, m41_w);
    bt1s_kernel<<<dim3(32,4,BB), 128>>>(feature);

    // Join: xqkv needs prep2's composite weights; fd2gv needs knn's indices.
    cudaStreamWaitEvent(0, ev2, 0);
    xqkv_kernel<<<dim3(16,4,BB), 128>>>();

    fd2gv_kernel<<<dim3(256,1,BB), 128, smemA>>>(xyz, fd2_b);

    fgfused_kernel<<<dim3(512,1,BB), 256, smemB>>>(fg2_b);

    k4_kernel<<<BB*NN, 256>>>(at_b, res);

    m4_kernel<<<dim3(64,1,BB), 128, smemD>>>(res, m41_b, m42_w, m42_b, out);
}

// round 16
// speedup vs baseline: 1.0511x; 1.0351x over previous
#include <cuda_runtime.h>
#include <cstdint>

#define BB 4
#define NN 2048
#define KK 16
#define DD 64
#define NK (NN*KK)
#define EPSV 1e-5f

// ---------------- f32x2 packed FMA helpers ----------------
__device__ __forceinline__ uint64_t pk2(float lo, float hi){
    uint64_t r;
    asm("mov.b64 %0, {%1, %2};" : "=l"(r) : "r"(__float_as_uint(lo)), "r"(__float_as_uint(hi)));
    return r;
}
__device__ __forceinline__ void fma2(uint64_t& d, uint64_t a, uint64_t b){
    asm("fma.rn.f32x2 %0, %1, %2, %0;" : "+l"(d) : "l"(a), "l"(b));
}
__device__ __forceinline__ void unpk2(uint64_t v, float& lo, float& hi){
    uint32_t l, h;
    asm("mov.b64 {%0, %1}, %2;" : "=r"(l), "=r"(h) : "l"(v));
    lo = __uint_as_float(l); hi = __uint_as_float(h);
}

// ---------------- scratch ----------------
__device__ float g_hx  [BB*128*NN];
__device__ float g_p1  [BB*128*NN];
__device__ float g_p2  [BB*128*NN];
__device__ float g_p3  [BB*128*NN];
__device__ float g_x   [BB*DD*NN];
__device__ float g_qkvt[BB*NN*192];
__device__ int   g_idx [BB*KK*NN];
__device__ float g_G   [BB*DD*NK];
__device__ float g_vr  [BB*DD*NK];
__device__ float g_at  [BB*DD*NK];
__device__ float g_fold[640];
__device__ float g_fd1f[256];
__device__ float g_wT  [4*64*64];
__device__ float g_w_bt1s[480*128];
__device__ float g_b_bt1s[128];
__device__ float g_w_xqkv[128*256];
__device__ float g_b_xqkv[256];
__device__ float g_w_fd2 [64*64];
__device__ float g_w_fg1 [64*256];
__device__ float g_w_fg2 [256*64];
__device__ float g_w_m41 [64*64];

// ---------------- prep ----------------
__global__ void prep_kernel(const float* __restrict__ fd_g, const float* __restrict__ fd1_b,
                            const float* __restrict__ fd_bb,
                            const float* __restrict__ fg_g, const float* __restrict__ fg1_b,
                            const float* __restrict__ fg_bb,
                            const float* __restrict__ at_w, const float* __restrict__ fd1_w,
                            const float* __restrict__ bt1_w, const float* __restrict__ bt1_b,
                            const float* __restrict__ bts_w, const float* __restrict__ bts_b,
                            const float* __restrict__ fd2_w,
                            const float* __restrict__ fg1_w, const float* __restrict__ fg2_w,
                            const float* __restrict__ m41_w)
{
    int t = blockIdx.x * blockDim.x + threadIdx.x;
    float inv = rsqrtf(1.f + EPSV);
    if (t < 64) {
        float s = fd_g[t]*inv;
        g_fd1f[t]       = fd1_w[t*3]   * s;
        g_fd1f[64+t]    = fd1_w[t*3+1] * s;
        g_fd1f[128+t]   = fd1_w[t*3+2] * s;
        g_fd1f[192+t]   = fd1_b[t]*s + fd_bb[t];
    }
    if (t < 256) { float s = fg_g[t]*inv; g_fold[128+t] = s; g_fold[384+t] = fg1_b[t]*s + fg_bb[t]; }
    if (t < 16384) {
        int r = t & 3, o = (t >> 2) & 63, c = t >> 8;
        g_wT[r*4096 + c*64 + o] = at_w[t];
        { int k = t >> 8, m = t & 255; g_w_fg1[k*256 + m] = fg1_w[m*64 + k]; }
        { int k = t >> 6, m = t & 63;  g_w_fg2[k*64 + m]  = fg2_w[m*256 + k]; }
    }
    if (t < 61440) { int k = t >> 7, m = t & 127;
        g_w_bt1s[t] = (m < 64) ? bt1_w[m*480 + k] : bts_w[(m-64)*480 + k]; }
    if (t < 128) g_b_bt1s[t] = (t < 64) ? bt1_b[t] : bts_b[t-64];
    if (t < 4096) { int k = t >> 6, m = t & 63;
        g_w_fd2[t] = fd2_w[m*64+k];
        g_w_m41[t] = m41_w[m*64+k]; }
}

// ---------------- prep2: composite x/qkv weights ----------------
__global__ void prep2_kernel(const float* __restrict__ bt2_w, const float* __restrict__ bt2_b,
                             const float* __restrict__ q_w, const float* __restrict__ q_b,
                             const float* __restrict__ k_w, const float* __restrict__ k_b,
                             const float* __restrict__ v_w, const float* __restrict__ v_b)
{
    int t = blockIdx.x * blockDim.x + threadIdx.x;
    if (t < 32768) {
        int m = t & 255, k = t >> 8;
        float val;
        if (k < 64) {
            if (m < 64) val = bt2_w[m*64 + k];
            else {
                int mm = m - 64;
                const float* wr = (mm < 64) ? q_w + mm*64
                                 : (mm < 128 ? k_w + (mm-64)*64 : v_w + (mm-128)*64);
                float s = 0.f;
                #pragma unroll 8
                for (int c = 0; c < 64; c++) s += wr[c] * bt2_w[c*64 + k];
                val = s;
            }
        } else {
            int kk = k - 64;
            if (m < 64) val = (m == kk) ? 1.f : 0.f;
            else {
                int mm = m - 64;
                val = (mm < 64) ? q_w[mm*64 + kk]
                     : (mm < 128 ? k_w[(mm-64)*64 + kk] : v_w[(mm-128)*64 + kk]);
            }
        }
        g_w_xqkv[k*256 + m] = val;
    } else if (t < 33024) {
        int m = t - 32768;
        if (m < 64) g_b_xqkv[m] = bt2_b[m];
        else {
            int mm = m - 64;
            const float* wr = (mm < 64) ? q_w + mm*64
                             : (mm < 128 ? k_w + (mm-64)*64 : v_w + (mm-128)*64);
            float s = (mm < 64) ? q_b[mm] : (mm < 128 ? k_b[mm-64] : v_b[mm-128]);
            #pragma unroll 8
            for (int c = 0; c < 64; c++) s += wr[c] * bt2_b[c];
            g_b_xqkv[m] = s;
        }
    }
}

// ---------------- KNN ----------------
__global__ void knn_kernel(const float* __restrict__ xyz)
{
    __shared__ float sx[NN], sy[NN], sz[NN], ssq[NN];
    int b  = blockIdx.x >> 7;
    int n0 = (blockIdx.x & 127) * 16;
    const float* xb = xyz + b*3*NN;
    for (int m = threadIdx.x; m < NN; m += blockDim.x) {
        float px = xb[m], py = xb[NN+m], pz = xb[2*NN+m];
        sx[m]=px; sy[m]=py; sz[m]=pz; ssq[m] = px*px + py*py + pz*pz;
    }
    __syncthreads();
    int warp = threadIdx.x >> 5, lane = threadIdx.x & 31;
    int n = n0 + warp;
    float px = sx[n], py = sy[n], pz = sz[n], sqn = ssq[n];

    float bv[17]; int bi[17];
    #pragma unroll
    for (int i = 0; i < 17; i++) { bv[i] = 3.4e38f; bi[i] = 0x7fffffff; }
    for (int m = lane; m < NN; m += 32) {
        float d2 = sqn + ssq[m] - 2.f*(px*sx[m] + py*sy[m] + pz*sz[m]);
        if (d2 < bv[16]) {
            bv[16] = d2; bi[16] = m;
            #pragma unroll
            for (int s = 16; s > 0; --s)
                if (bv[s] < bv[s-1]) {
                    float tv = bv[s]; bv[s] = bv[s-1]; bv[s-1] = tv;
                    int   ti = bi[s]; bi[s] = bi[s-1]; bi[s-1] = ti;
                }
        }
    }
    for (int t = 0; t < 17; ++t) {
        float hv = bv[0]; int hi = bi[0];
        float v = hv; int id = hi;
        #pragma unroll
        for (int off = 16; off; off >>= 1) {
            float ov = __shfl_xor_sync(0xffffffffu, v, off);
            int   oi = __shfl_xor_sync(0xffffffffu, id, off);
            if (ov < v || (ov == v && oi < id)) { v = ov; id = oi; }
        }
        if (t > 0 && lane == 0) g_idx[b*KK*NN + (t-1)*NN + n] = id;
        if (hv == v && hi == id) {
            #pragma unroll
            for (int s = 0; s < 16; ++s) { bv[s] = bv[s+1]; bi[s] = bi[s+1]; }
            bv[16] = 3.4e38f; bi[16] = 0x7fffffff;
        }
    }
}

// ---------------- bt1s split-K(4) GEMM (b-halved) ----------------
__global__ void __launch_bounds__(128) bt1s_kernel(const float* __restrict__ feature, int bz)
{
    constexpr int KC = 8;
    __shared__ __align__(16) float sW[2][KC][128];
    __shared__ __align__(16) float sX[2][KC][64];
    int tid = threadIdx.x;
    int b = blockIdx.z + bz;
    int split = blockIdx.y;
    int bn0 = blockIdx.x * 64;
    const float* Wt = g_w_bt1s + (size_t)split*120*128;
    const float* Xb = feature + (size_t)b*480*NN + (size_t)split*120*NN;
    float* Cb = (split == 0 ? g_hx : (split == 1 ? g_p1 : (split == 2 ? g_p2 : g_p3)))
                + (size_t)b*128*NN;

    float4 wr[2], xr1;
    uint64_t acc2[8][4];
    #pragma unroll
    for (int i = 0; i < 8; i++)
        #pragma unroll
        for (int j = 0; j < 4; j++) acc2[i][j] = 0ull;
    int tx = tid & 7, ty = tid >> 3;
    int rm = ty*8, rn = tx*8;

    {
        #pragma unroll
        for (int i = 0; i < 2; i++) { int t = tid + i*128; int k = t>>5, m4 = (t&31)*4;
            wr[i] = *(const float4*)(Wt + (size_t)k*128 + m4); }
        { int k = tid >> 4, n4 = (tid & 15)*4;
          xr1 = *(const float4*)(Xb + (size_t)k*NN + bn0 + n4); }
        #pragma unroll
        for (int i = 0; i < 2; i++) { int t = tid + i*128; int k = t>>5, m4 = (t&31)*4;
            *(float4*)&sW[0][k][m4] = wr[i]; }
        { int k = tid >> 4, n4 = (tid & 15)*4; *(float4*)&sX[0][k][n4] = xr1; }
    }
    __syncthreads();

    for (int c = 0; c < 15; ++c) {
        if (c + 1 < 15) {
            int k0 = (c+1)*KC;
            #pragma unroll
            for (int i = 0; i < 2; i++) { int t = tid + i*128; int k = t>>5, m4 = (t&31)*4;
                wr[i] = *(const float4*)(Wt + (size_t)(k0+k)*128 + m4); }
            { int k = tid >> 4, n4 = (tid & 15)*4;
              xr1 = *(const float4*)(Xb + (size_t)(k0 + (tid>>4))*NN + bn0 + n4); }
        }
        int buf = c & 1;
        #pragma unroll
        for (int k = 0; k < KC; ++k) {
            ulonglong2 bq0 = *(const ulonglong2*)&sX[buf][k][rn];
            ulonglong2 bq1 = *(const ulonglong2*)&sX[buf][k][rn+4];
            uint64_t bp[4] = {bq0.x, bq0.y, bq1.x, bq1.y};
            float4 a0 = *(const float4*)&sW[buf][k][rm];
            float4 a1 = *(const float4*)&sW[buf][k][rm+4];
            float av[8] = {a0.x,a0.y,a0.z,a0.w,a1.x,a1.y,a1.z,a1.w};
            #pragma unroll
            for (int i = 0; i < 8; i++) {
                uint64_t ap = pk2(av[i], av[i]);
                #pragma unroll
                for (int j = 0; j < 4; j++) fma2(acc2[i][j], ap, bp[j]);
            }
        }
        if (c + 1 < 15) {
            int nb = (c+1) & 1;
            #pragma unroll
            for (int i = 0; i < 2; i++) { int t = tid + i*128; int k = t>>5, m4 = (t&31)*4;
                *(float4*)&sW[nb][k][m4] = wr[i]; }
            { int k = tid >> 4, n4 = (tid & 15)*4; *(float4*)&sX[nb][k][n4] = xr1; }
        }
        __syncthreads();
    }

    #pragma unroll
    for (int i = 0; i < 8; i++) {
        int row = rm + i;
        float v[8];
        #pragma unroll
        for (int j = 0; j < 4; j++) unpk2(acc2[i][j], v[2*j], v[2*j+1]);
        *(float4*)(Cb + (size_t)row*NN + bn0 + rn)     = make_float4(v[0],v[1],v[2],v[3]);
        *(float4*)(Cb + (size_t)row*NN + bn0 + rn + 4) = make_float4(v[4],v[5],v[6],v[7]);
    }
}

__device__ __forceinline__ float4 hx_load(const float* p0, const float* p1,
                                          const float* p2, const float* p3,
                                          size_t off, int kglob)
{
    float4 a = *(const float4*)(p0 + off);
    float4 c = *(const float4*)(p1 + off);
    float4 d = *(const float4*)(p2 + off);
    float4 e = *(const float4*)(p3 + off);
    float bs = g_b_bt1s[kglob];
    float4 r = make_float4(a.x+c.x+d.x+e.x+bs, a.y+c.y+d.y+e.y+bs,
                           a.z+c.z+d.z+e.z+bs, a.w+c.w+d.w+e.w+bs);
    if (kglob < 64) {
        r.x = fmaxf(r.x, 0.f); r.y = fmaxf(r.y, 0.f);
        r.z = fmaxf(r.z, 0.f); r.w = fmaxf(r.w, 0.f);
    }
    return r;
}

// ---------------- xqkv (b-halved) ----------------
__global__ void __launch_bounds__(128) xqkv_kernel(int bz)
{
    constexpr int KC = 8;
    __shared__ __align__(16) float sW[2][KC][64];
    __shared__ __align__(16) float sX[2][KC][128];
    int tid = threadIdx.x;
    int b = blockIdx.z + bz;
    int bn0 = blockIdx.x * 128;
    int bm0 = blockIdx.y * 64;
    const float* p0 = g_hx + (size_t)b * 128 * NN;
    const float* p1 = g_p1 + (size_t)b * 128 * NN;
    const float* p2 = g_p2 + (size_t)b * 128 * NN;
    const float* p3 = g_p3 + (size_t)b * 128 * NN;

    float4 wr1, xr[2];
    uint64_t acc2[8][4];
    #pragma unroll
    for (int i = 0; i < 8; i++)
        #pragma unroll
        for (int j = 0; j < 4; j++) acc2[i][j] = 0ull;
    int tx = tid & 15, ty = tid >> 4;
    int rm = ty*8, rn = tx*8;
    int wk = tid >> 4;
    int wm = (tid & 15) * 4;

    {
        wr1 = *(const float4*)(g_w_xqkv + (size_t)wk*256 + bm0 + wm);
        #pragma unroll
        for (int i = 0; i < 2; i++) { int t = tid + i*128; int k = t >> 5, n4 = t & 31;
            xr[i] = hx_load(p0, p1, p2, p3, (size_t)k*NN + bn0 + n4*4, k); }
        *(float4*)&sW[0][wk][wm] = wr1;
        #pragma unroll
        for (int i = 0; i < 2; i++) { int t = tid + i*128; int k = t >> 5, n4 = t & 31;
            *(float4*)&sX[0][k][n4*4] = xr[i]; }
    }
    __syncthreads();

    for (int c = 0; c < 16; ++c) {
        if (c + 1 < 16) {
            int k0 = (c+1)*KC;
            wr1 = *(const float4*)(g_w_xqkv + (size_t)(k0+wk)*256 + bm0 + wm);
            #pragma unroll
            for (int i = 0; i < 2; i++) { int t = tid + i*128; int k = t >> 5, n4 = t & 31;
                xr[i] = hx_load(p0, p1, p2, p3, (size_t)(k0+k)*NN + bn0 + n4*4, k0+k); }
        }
        int buf = c & 1;
        #pragma unroll
        for (int k = 0; k < KC; ++k) {
            ulonglong2 bq0 = *(const ulonglong2*)&sX[buf][k][rn];
            ulonglong2 bq1 = *(const ulonglong2*)&sX[buf][k][rn+4];
            uint64_t bp[4] = {bq0.x, bq0.y, bq1.x, bq1.y};
            float4 a0 = *(const float4*)&sW[buf][k][rm];
            float4 a1 = *(const float4*)&sW[buf][k][rm+4];
            float av[8] = {a0.x,a0.y,a0.z,a0.w,a1.x,a1.y,a1.z,a1.w};
            #pragma unroll
            for (int i = 0; i < 8; i++) {
                uint64_t ap = pk2(av[i], av[i]);
                #pragma unroll
                for (int j = 0; j < 4; j++) fma2(acc2[i][j], ap, bp[j]);
            }
        }
        if (c + 1 < 16) {
            int nb = (c+1) & 1;
            *(float4*)&sW[nb][wk][wm] = wr1;
            #pragma unroll
            for (int i = 0; i < 2; i++) { int t = tid + i*128; int k = t >> 5, n4 = t & 31;
                *(float4*)&sX[nb][k][n4*4] = xr[i]; }
        }
        __syncthreads();
    }

    float v[8][8];
    #pragma unroll
    for (int i = 0; i < 8; i++) {
        float bs = g_b_xqkv[bm0 + rm + i];
        #pragma unroll
        for (int j = 0; j < 4; j++) {
            float lo, hi;
            unpk2(acc2[i][j], lo, hi);
            v[i][2*j] = lo + bs; v[i][2*j+1] = hi + bs;
        }
    }
    if (blockIdx.y == 0) {
        #pragma unroll
        for (int i = 0; i < 8; i++) {
            int row = rm + i;
            *(float4*)(g_x + ((size_t)(b*64+row))*NN + bn0 + rn)
                = make_float4(v[i][0],v[i][1],v[i][2],v[i][3]);
            *(float4*)(g_x + ((size_t)(b*64+row))*NN + bn0 + rn + 4)
                = make_float4(v[i][4],v[i][5],v[i][6],v[i][7]);
        }
    } else {
        int qbase = bm0 + rm - 64;
        #pragma unroll
        for (int j = 0; j < 8; j++) {
            int n = bn0 + rn + j;
            float* dst = g_qkvt + ((size_t)(b*NN) + n)*192 + qbase;
            *(float4*)dst       = make_float4(v[0][j],v[1][j],v[2][j],v[3][j]);
            *(float4*)(dst + 4) = make_float4(v[4][j],v[5][j],v[6][j],v[7][j]);
        }
    }
}

// ---------------- fused posenc(fd1) + fd2 GEMM + G/Vrel build (b-halved) ----------------
__global__ void __launch_bounds__(128) fd2gv_kernel(const float* __restrict__ xyz,
                                                    const float* __restrict__ fd2_b, int bz)
{
    extern __shared__ __align__(16) float dynA[];
    float* sW = dynA;
    float* sT = dynA + 64*68;
    float* sF = dynA + 64*68 + 64*132;
    int tid = threadIdx.x;
    int b = blockIdx.z + bz;
    int bn0 = blockIdx.x * 128;
    int tx = tid & 15, ty = tid >> 4;
    int rn = tx*8, rm = ty*8;

    #pragma unroll
    for (int i = 0; i < 8; i++) { int t = tid + i*128; int k = t>>4, m4 = (t&15)*4;
        *(float4*)&sW[k*68 + m4] = *(const float4*)(g_w_fd2 + k*64 + m4); }
    sF[tid] = g_fd1f[tid];
    sF[tid+128] = g_fd1f[tid+128];

    int col = bn0 + tid;
    int np = col >> 4, jp = col & 15;
    int idg = g_idx[b*KK*NN + jp*NN + np];
    const float* xb = xyz + b*3*NN;
    float rx = xb[np]      - xb[idg];
    float ry = xb[NN+np]   - xb[NN+idg];
    float rz = xb[2*NN+np] - xb[2*NN+idg];
    __syncthreads();
    #pragma unroll 8
    for (int m = 0; m < 64; ++m) {
        float v = sF[m]*rx + sF[64+m]*ry + sF[128+m]*rz + sF[192+m];
        sT[m*132 + tid] = fmaxf(v, 0.f);
    }
    __syncthreads();

    uint64_t acc[8][4];
    #pragma unroll
    for (int i = 0; i < 8; i++)
        #pragma unroll
        for (int j = 0; j < 4; j++) acc[i][j] = 0ull;
    #pragma unroll 4
    for (int k = 0; k < 64; ++k) {
        ulonglong2 b0 = *(const ulonglong2*)&sT[k*132 + rn];
        ulonglong2 b1 = *(const ulonglong2*)&sT[k*132 + rn + 4];
        float4 a0 = *(const float4*)&sW[k*68 + rm];
        float4 a1 = *(const float4*)&sW[k*68 + rm + 4];
        float av[8] = {a0.x,a0.y,a0.z,a0.w,a1.x,a1.y,a1.z,a1.w};
        #pragma unroll
        for (int i = 0; i < 8; i++) {
            uint64_t ap = pk2(av[i], av[i]);
            fma2(acc[i][0], ap, b0.x); fma2(acc[i][1], ap, b0.y);
            fma2(acc[i][2], ap, b1.x); fma2(acc[i][3], ap, b1.y);
        }
    }

    int col0 = bn0 + rn;
    int n = col0 >> 4, j0 = col0 & 15;
    float qv[8], bs[8];
    const float* qp = g_qkvt + ((size_t)b*NN + n)*192 + rm;
    *(float4*)&qv[0] = *(const float4*)qp;
    *(float4*)&qv[4] = *(const float4*)(qp + 4);
    #pragma unroll
    for (int i = 0; i < 8; i++) bs[i] = fd2_b[rm + i];

    #pragma unroll
    for (int g = 0; g < 2; ++g) {
        float ka[4][8], va[4][8];
        #pragma unroll
        for (int jj = 0; jj < 4; jj++) {
            int id = g_idx[b*KK*NN + (j0 + g*4 + jj)*NN + n];
            const float* kp = g_qkvt + ((size_t)b*NN + id)*192 + 64 + rm;
            *(float4*)&ka[jj][0] = *(const float4*)kp;
            *(float4*)&ka[jj][4] = *(const float4*)(kp + 4);
            *(float4*)&va[jj][0] = *(const float4*)(kp + 64);
            *(float4*)&va[jj][4] = *(const float4*)(kp + 68);
        }
        #pragma unroll
        for (int i = 0; i < 8; i++) {
            float p0,p1,p2,p3;
            unpk2(acc[i][2*g],   p0, p1);
            unpk2(acc[i][2*g+1], p2, p3);
            p0 += bs[i]; p1 += bs[i]; p2 += bs[i]; p3 += bs[i];
            size_t off = ((size_t)(b*64 + rm + i))*NK + col0 + g*4;
            *(float4*)(g_G  + off) = make_float4(qv[i]-ka[0][i]+p0, qv[i]-ka[1][i]+p1,
                                                 qv[i]-ka[2][i]+p2, qv[i]-ka[3][i]+p3);
            *(float4*)(g_vr + off) = make_float4(va[0][i]+p0, va[1][i]+p1,
                                                 va[2][i]+p2, va[3][i]+p3);
        }
    }
}

// ---------------- fused fg1 + relu + fg2 (b-halved) ----------------
__global__ void __launch_bounds__(256) fgfused_kernel(const float* __restrict__ fg2_b, int bz)
{
    extern __shared__ __align__(16) float dynB[];
    float* sG = dynB;
    float* sH = dynB + 64*68;
    float* sW = dynB + 64*68 + 256*68;
    int tid = threadIdx.x;
    int b = blockIdx.z + bz;
    int col0 = blockIdx.x * 64;

    #pragma unroll
    for (int i = 0; i < 4; i++) { int t = tid + i*256; int c = t>>4, f4 = (t&15)*4;
        *(float4*)&sG[c*68 + f4] = *(const float4*)(g_G + ((size_t)(b*64+c))*NK + col0 + f4); }

    int tx = tid & 7, ty = tid >> 3;
    int rn = tx*8, rm = ty*8;
    int lk1 = tid >> 6, lm1 = (tid & 63) * 4;
    uint64_t acc[8][4];
    #pragma unroll
    for (int i = 0; i < 8; i++)
        #pragma unroll
        for (int j = 0; j < 4; j++) acc[i][j] = 0ull;
    float4 wpre[4];
    #pragma unroll
    for (int i = 0; i < 4; i++)
        wpre[i] = *(const float4*)(g_w_fg1 + (size_t)(i*4 + lk1)*256 + lm1);
    for (int kc = 0; kc < 4; ++kc) {
        __syncthreads();
        #pragma unroll
        for (int i = 0; i < 4; i++)
            *(float4*)&sW[(i*4 + lk1)*256 + lm1] = wpre[i];
        __syncthreads();
        if (kc < 3) {
            #pragma unroll
            for (int i = 0; i < 4; i++)
                wpre[i] = *(const float4*)(g_w_fg1 + (size_t)((kc+1)*16 + i*4 + lk1)*256 + lm1);
        }
        #pragma unroll
        for (int k = 0; k < 16; ++k) {
            int kk = kc*16 + k;
            ulonglong2 b0 = *(const ulonglong2*)&sG[kk*68 + rn];
            ulonglong2 b1 = *(const ulonglong2*)&sG[kk*68 + rn + 4];
            float4 a0 = *(const float4*)&sW[k*256 + rm];
            float4 a1 = *(const float4*)&sW[k*256 + rm + 4];
            float av[8] = {a0.x,a0.y,a0.z,a0.w,a1.x,a1.y,a1.z,a1.w};
            #pragma unroll
            for (int i = 0; i < 8; i++) {
                uint64_t ap = pk2(av[i], av[i]);
                fma2(acc[i][0], ap, b0.x); fma2(acc[i][1], ap, b0.y);
                fma2(acc[i][2], ap, b1.x); fma2(acc[i][3], ap, b1.y);
            }
        }
    }
    #pragma unroll
    for (int i = 0; i < 8; i++) {
        int row = rm + i;
        float sc = g_fold[128 + row], bb2 = g_fold[384 + row];
        float v[8];
        #pragma unroll
        for (int j = 0; j < 4; j++) unpk2(acc[i][j], v[2*j], v[2*j+1]);
        #pragma unroll
        for (int j = 0; j < 8; j++) v[j] = fmaxf(v[j]*sc + bb2, 0.f);
        *(float4*)&sH[row*68 + rn]     = make_float4(v[0],v[1],v[2],v[3]);
        *(float4*)&sH[row*68 + rn + 4] = make_float4(v[4],v[5],v[6],v[7]);
    }

    int tx2 = tid & 15, ty2 = tid >> 4;
    int rn2 = tx2*4, rm2 = ty2*4;
    int lk2 = tid >> 4, lm2 = (tid & 15) * 4;
    uint64_t accB[4][2];
    #pragma unroll
    for (int i = 0; i < 4; i++) { accB[i][0] = 0ull; accB[i][1] = 0ull; }
    #pragma unroll
    for (int i = 0; i < 4; i++)
        wpre[i] = *(const float4*)(g_w_fg2 + (size_t)(i*16 + lk2)*64 + lm2);
    for (int kc2 = 0; kc2 < 4; ++kc2) {
        __syncthreads();
        #pragma unroll
        for (int i = 0; i < 4; i++)
            *(float4*)&sW[(i*16 + lk2)*64 + lm2] = wpre[i];
        __syncthreads();
        if (kc2 < 3) {
            #pragma unroll
            for (int i = 0; i < 4; i++)
                wpre[i] = *(const float4*)(g_w_fg2 + (size_t)((kc2+1)*64 + i*16 + lk2)*64 + lm2);
        }
        #pragma unroll 4
        for (int k = 0; k < 64; ++k) {
            int kk = kc2*64 + k;
            ulonglong2 b2 = *(const ulonglong2*)&sH[kk*68 + rn2];
            float4 a4 = *(const float4*)&sW[k*64 + rm2];
            float av[4] = {a4.x, a4.y, a4.z, a4.w};
            #pragma unroll
            for (int i = 0; i < 4; i++) {
                uint64_t ap = pk2(av[i], av[i]);
                fma2(accB[i][0], ap, b2.x); fma2(accB[i][1], ap, b2.y);
            }
        }
    }
    #pragma unroll
    for (int i = 0; i < 4; i++) {
        int row = rm2 + i;
        float bb = __ldg(fg2_b + row);
        float v0,v1,v2,v3;
        unpk2(accB[i][0], v0, v1);
        unpk2(accB[i][1], v2, v3);
        *(float4*)(g_at + ((size_t)(b*64+row))*NK + col0 + rn2) =
            make_float4(v0+bb, v1+bb, v2+bb, v3+bb);
    }
}

// ---------------- fused ConvT(4,1) + softmax + weighted sum + identity (bn-offset) ----------------
__global__ void __launch_bounds__(256) k4_kernel(const float* __restrict__ at_b,
                                                 float* __restrict__ res_out, int bnoff)
{
    __shared__ __align__(16) float s_a[64*16];
    __shared__ float s_v[16*64];
    __shared__ float s_s[16][8];
    __shared__ float s_out[256];
    int bn = blockIdx.x + bnoff;
    int b = bn >> 11, n = bn & 2047;
    int tid = threadIdx.x;
    int o = tid & 63, r = tid >> 6;
    int lane = tid & 31, warp = tid >> 5;
    {
        int c = tid >> 2, fq = (tid & 3) * 4;
        size_t base = ((size_t)(b*64 + c)*2048 + n)*16 + fq;
        float4 a4 = *(const float4*)(g_at + base);
        *(float4*)(s_a + c*16 + fq) = a4;
        float4 v4 = *(const float4*)(g_vr + base);
        s_v[(fq+0)*64 + c] = v4.x;
        s_v[(fq+1)*64 + c] = v4.y;
        s_v[(fq+2)*64 + c] = v4.z;
        s_v[(fq+3)*64 + c] = v4.w;
    }
    __syncthreads();

    float bo = at_b[o];
    uint64_t y2[8];
    uint64_t bo2 = pk2(bo, bo);
    #pragma unroll
    for (int f = 0; f < 8; f++) y2[f] = bo2;
    const float* w = g_wT + r*4096 + o;
    #pragma unroll 4
    for (int c = 0; c < 64; c++) {
        uint64_t wp = pk2(w[c*64], w[c*64]);
        const ulonglong2* ap = (const ulonglong2*)(s_a + c*16);
        ulonglong2 q0 = ap[0], q1 = ap[1];
        fma2(y2[0], wp, q0.x); fma2(y2[1], wp, q0.y);
        fma2(y2[2], wp, q1.x); fma2(y2[3], wp, q1.y);
        ulonglong2 q2 = ap[2], q3 = ap[3];
        fma2(y2[4], wp, q2.x); fma2(y2[5], wp, q2.y);
        fma2(y2[6], wp, q3.x); fma2(y2[7], wp, q3.y);
    }
    float y[16];
    #pragma unroll
    for (int f = 0; f < 8; f++) unpk2(y2[f], y[2*f], y[2*f+1]);

    #pragma unroll
    for (int f = 0; f < 16; f++) {
        float e = __expf(y[f]);
        y[f] = e;
        float sm = e;
        #pragma unroll
        for (int off = 16; off; off >>= 1) sm += __shfl_xor_sync(0xffffffffu, sm, off);
        if (lane == 0) s_s[f][warp] = sm;
    }
    __syncthreads();
    float acc = 0.f;
    #pragma unroll
    for (int f = 0; f < 16; f++) {
        float sum = s_s[f][2*r] + s_s[f][2*r+1];
        acc = fmaf(__fdividef(y[f], sum), s_v[f*64 + o], acc);
    }
    acc += g_x[(size_t)b*131072 + o*2048 + n];
    s_out[o*4 + r] = acc;
    __syncthreads();
    if (tid < 64) {
        float4 ov = *(const float4*)(s_out + tid*4);
        *(float4*)(res_out + (size_t)b*524288 + (size_t)tid*8192 + n*4) = ov;
    }
}

// ---------------- fused m41 + relu + m42 (b-halved) ----------------
__global__ void __launch_bounds__(128) m4_kernel(const float* __restrict__ res,
                                                 const float* __restrict__ m41_b,
                                                 const float* __restrict__ m42_w,
                                                 const float* __restrict__ m42_b,
                                                 float* __restrict__ out, int bz)
{
    extern __shared__ __align__(16) float dynD[];
    float* sWm  = dynD;
    float* sres = dynD + 64*68;
    float* sch  = dynD + 64*68 + 64*132;
    int tid = threadIdx.x;
    int b = blockIdx.z + bz;
    int bn0 = blockIdx.x * 128;
    int tx = tid & 15, ty = tid >> 4;
    int rn = tx*8, rm = ty*8;

    #pragma unroll
    for (int i = 0; i < 8; i++) { int t = tid + i*128; int k = t>>4, m4 = (t&15)*4;
        *(float4*)&sWm[k*68 + m4] = *(const float4*)(g_w_m41 + k*64 + m4); }
    #pragma unroll
    for (int i = 0; i < 16; i++) { int t = tid + i*128; int k = t>>5, f = (t&31)*4;
        *(float4*)&sres[k*132 + f] = *(const float4*)(res + ((size_t)(b*64+k))*8192 + bn0 + f); }
    __syncthreads();

    uint64_t acc[8][4];
    #pragma unroll
    for (int i = 0; i < 8; i++)
        #pragma unroll
        for (int j = 0; j < 4; j++) acc[i][j] = 0ull;
    #pragma unroll 4
    for (int k = 0; k < 64; ++k) {
        ulonglong2 b0 = *(const ulonglong2*)&sres[k*132 + rn];
        ulonglong2 b1 = *(const ulonglong2*)&sres[k*132 + rn + 4];
        float4 a0 = *(const float4*)&sWm[k*68 + rm];
        float4 a1 = *(const float4*)&sWm[k*68 + rm + 4];
        float av[8] = {a0.x,a0.y,a0.z,a0.w,a1.x,a1.y,a1.z,a1.w};
        #pragma unroll
        for (int i = 0; i < 8; i++) {
            uint64_t ap = pk2(av[i], av[i]);
            fma2(acc[i][0], ap, b0.x); fma2(acc[i][1], ap, b0.y);
            fma2(acc[i][2], ap, b1.x); fma2(acc[i][3], ap, b1.y);
        }
    }
    #pragma unroll
    for (int i = 0; i < 8; i++) {
        int row = rm + i;
        float bs = m41_b[row];
        float v[8];
        #pragma unroll
        for (int j = 0; j < 4; j++) unpk2(acc[i][j], v[2*j], v[2*j+1]);
        #pragma unroll
        for (int j = 0; j < 8; j++) sch[row*132 + rn + j] = fmaxf(v[j] + bs, 0.f);
    }
    __syncthreads();
    if (tid < 48) *(float4*)&sWm[tid*4] = *(const float4*)(m42_w + tid*4);
    __syncthreads();

    float a0 = m42_b[0], a1 = m42_b[1], a2 = m42_b[2];
    #pragma unroll 8
    for (int k = 0; k < 64; ++k) {
        float xv = sch[k*132 + tid];
        a0 = fmaf(sWm[k],     xv, a0);
        a1 = fmaf(sWm[64+k],  xv, a1);
        a2 = fmaf(sWm[128+k], xv, a2);
    }
    out[(size_t)(b*3+0)*8192 + bn0 + tid] = a0;
    out[(size_t)(b*3+1)*8192 + bn0 + tid] = a1;
    out[(size_t)(b*3+2)*8192 + bn0 + tid] = a2;
}

// ---------------- launch: dual half-batch pipelines ----------------
extern "C" void kernel_launch(void* const* d_in, const int* in_sizes, int n_in,
                              void* d_out, int out_size)
{
    const float* feature = (const float*)d_in[0];
    const float* xyz     = (const float*)d_in[1];
    const float* bt1_w = (const float*)d_in[2];  const float* bt1_b = (const float*)d_in[3];
    const float* bt2_w = (const float*)d_in[4];  const float* bt2_b = (const float*)d_in[5];
    const float* bts_w = (const float*)d_in[6];  const float* bts_b = (const float*)d_in[7];
    const float* q_w   = (const float*)d_in[8];  const float* q_b   = (const float*)d_in[9];
    const float* k_w   = (const float*)d_in[10]; const float* k_b   = (const float*)d_in[11];
    const float* v_w   = (const float*)d_in[12]; const float* v_b   = (const float*)d_in[13];
    const float* fd1_w = (const float*)d_in[14]; const float* fd1_b = (const float*)d_in[15];
    const float* fd_g  = (const float*)d_in[16]; const float* fd_bb = (const float*)d_in[17];
    const float* fd2_w = (const float*)d_in[18]; const float* fd2_b = (const float*)d_in[19];
    const float* fg1_w = (const float*)d_in[20]; const float* fg1_b = (const float*)d_in[21];
    const float* fg_g  = (const float*)d_in[22]; const float* fg_bb = (const float*)d_in[23];
    const float* fg2_w = (const float*)d_in[24]; const float* fg2_b = (const float*)d_in[25];
    const float* at_w  = (const float*)d_in[26]; const float* at_b  = (const float*)d_in[27];
    const float* m41_w = (const float*)d_in[28]; const float* m41_b = (const float*)d_in[29];
    const float* m42_w = (const float*)d_in[30]; const float* m42_b = (const float*)d_in[31];

    float* out = (float*)d_out;
    float* res = out + BB*3*4*NN;

    const int smemA = (64*68 + 64*132 + 256) * 4;      // 52224
    const int smemB = (64*68 + 256*68 + 4096) * 4;     // 103424
    const int smemD = (64*68 + 64*132 + 64*132) * 4;   // 84992
    static bool attr_done = false;
    static cudaStream_t s2 = nullptr;
    static cudaEvent_t ev1 = nullptr, evK = nullptr, evP = nullptr, evF = nullptr;
    if (!attr_done) {
        cudaFuncSetAttribute(fd2gv_kernel,   cudaFuncAttributeMaxDynamicSharedMemorySize, smemA);
        cudaFuncSetAttribute(fgfused_kernel, cudaFuncAttributeMaxDynamicSharedMemorySize, smemB);
        cudaFuncSetAttribute(m4_kernel,      cudaFuncAttributeMaxDynamicSharedMemorySize, smemD);
        cudaStreamCreateWithFlags(&s2, cudaStreamNonBlocking);
        cudaEventCreateWithFlags(&ev1, cudaEventDisableTiming);
        cudaEventCreateWithFlags(&evK, cudaEventDisableTiming);
        cudaEventCreateWithFlags(&evP, cudaEventDisableTiming);
        cudaEventCreateWithFlags(&evF, cudaEventDisableTiming);
        attr_done = true;
    }

    // fork
    cudaEventRecord(ev1, 0);
    cudaStreamWaitEvent(s2, ev1, 0);

    // side stream: prep2 + knn (all b), then half-chain B (b=2,3)
    prep2_kernel<<<130, 256, 0, s2>>>(bt2_w, bt2_b, q_w, q_b, k_w, k_b, v_w, v_b);
    knn_kernel<<<BB*NN/16, 512, 0, s2>>>(xyz);
    cudaEventRecord(evK, s2);          // prep2 + knn done

    // main stream: prep, then half-chain A (b=0,1)
    prep_kernel<<<256, 256>>>(fd_g, fd1_b, fd_bb, fg_g, fg1_b, fg_bb, at_w, fd1_w,
                              bt1_w, bt1_b, bts_w, bts_b,
                              fd2_w, fg1_w, fg2_w, m41_w);
    cudaEventRecord(evP, 0);           // prep done (side chain needs g_w_bt1s etc.)

    bt1s_kernel<<<dim3(32,4,2), 128>>>(feature, 0);
    cudaStreamWaitEvent(0, evK, 0);    // main needs prep2 (xqkv) + knn (fd2gv)
    xqkv_kernel<<<dim3(16,4,2), 128>>>(0);
    fd2gv_kernel<<<dim3(256,1,2), 128, smemA>>>(xyz, fd2_b, 0);
    fgfused_kernel<<<dim3(512,1,2), 256, smemB>>>(fg2_b, 0);
    k4_kernel<<<BB*NN/2, 256>>>(at_b, res, 0);
    m4_kernel<<<dim3(64,1,2), 128, smemD>>>(res, m41_b, m42_w, m42_b, out, 0);

    // side stream half-chain B
    cudaStreamWaitEvent(s2, evP, 0);   // side needs prep's weights
    bt1s_kernel<<<dim3(32,4,2), 128, 0, s2>>>(feature, 2);
    xqkv_kernel<<<dim3(16,4,2), 128, 0, s2>>>(2);
    fd2gv_kernel<<<dim3(256,1,2), 128, smemA, s2>>>(xyz, fd2_b, 2);
    fgfused_kernel<<<dim3(512,1,2), 256, smemB, s2>>>(fg2_b, 2);
    k4_kernel<<<BB*NN/2, 256, 0, s2>>>(at_b, res, BB*NN/2);
    m4_kernel<<<dim3(64,1,2), 128, smemD, s2>>>(res, m41_b, m42_w, m42_b, out, 2);
    cudaEventRecord(evF, s2);

    // join
    cudaStreamWaitEvent(0, evF, 0);
}